// round 1
// baseline (speedup 1.0000x reference)
#include <cuda_runtime.h>
#include <math.h>

#define NN   50000
#define EE   1600000
#define FIN  512
#define HH   8
#define C1   8
#define HID  64
#define NCLS 7
#define NEG_SLOPE 0.2f

// ---------------- scratch (device globals; no runtime allocation) ------------
__device__ float    g_xh   [NN * HID];   // x @ W1
__device__ float    g_si   [NN * HH];
__device__ float    g_sj   [NN * HH];
__device__ unsigned g_amax [NN * HH];    // monotonic-uint encoded float max
__device__ float    g_den  [NN * HH];
__device__ float    g_D    [NN];
__device__ float    g_B    [NN];
__device__ float    g_Dinv [NN];
__device__ float    g_Binv [NN];
__device__ float    g_oute [NN * HID];   // hyperedge accumulator, layer 1
__device__ float    g_h1   [NN * HID];   // node output layer 1 (then elu'd)
__device__ float    g_alpha[EE * HH];    // per-edge attention (ex, then alpha)
__device__ float    g_xh2  [NN * 8];     // h @ W2, padded 7->8
__device__ float    g_oute2[NN * 8];
__device__ float    g_out2 [NN * 8];

// monotonic mapping: float -> uint preserving order for atomicMax
__device__ __forceinline__ unsigned f2u_mono(float x) {
    unsigned u = __float_as_uint(x);
    return (u & 0x80000000u) ? ~u : (u | 0x80000000u);
}
__device__ __forceinline__ float u2f_mono(unsigned u) {
    return (u & 0x80000000u) ? __uint_as_float(u & 0x7fffffffu)
                             : __uint_as_float(~u);
}
__device__ __forceinline__ float lrelu(float a) {
    return a > 0.f ? a : NEG_SLOPE * a;
}

// ---------------- kernels ----------------------------------------------------

__global__ void k_init() {
    int i = blockIdx.x * blockDim.x + threadIdx.x;
    int stride = gridDim.x * blockDim.x;
    for (int t = i; t < NN; t += stride) { g_D[t] = 0.f; g_B[t] = 0.f; }
    for (int t = i; t < NN * HH; t += stride) {
        g_amax[t] = 0u; g_den[t] = 0.f; g_oute2[t] = 0.f; g_out2[t] = 0.f;
    }
    for (int t = i; t < NN * HID; t += stride) { g_oute[t] = 0.f; g_h1[t] = 0.f; }
}

// tiled fp32 GEMM: g_xh[N,64] = X[N,512] @ W1[512,64]
#define BM 64
#define BN 64
#define BK 32
__global__ void k_gemm1(const float* __restrict__ X, const float* __restrict__ W) {
    __shared__ float As[BK][BM + 1];
    __shared__ float Bs[BK][BN];
    int bm = blockIdx.x * BM;
    int tid = threadIdx.x;                 // 256 threads
    int tx = tid & 15, ty = tid >> 4;      // 16x16
    float acc[4][4];
#pragma unroll
    for (int i = 0; i < 4; i++)
#pragma unroll
        for (int j = 0; j < 4; j++) acc[i][j] = 0.f;

    for (int k0 = 0; k0 < FIN; k0 += BK) {
#pragma unroll
        for (int l = 0; l < 2; l++) {            // A tile: 64x32 = 512 float4
            int p = tid + l * 256;
            int m = p >> 3;                       // 8 float4 per row
            int k4 = (p & 7) << 2;
            float4 v = make_float4(0.f, 0.f, 0.f, 0.f);
            if (bm + m < NN) v = *(const float4*)&X[(size_t)(bm + m) * FIN + k0 + k4];
            As[k4 + 0][m] = v.x; As[k4 + 1][m] = v.y;
            As[k4 + 2][m] = v.z; As[k4 + 3][m] = v.w;
        }
#pragma unroll
        for (int l = 0; l < 2; l++) {            // B tile: 32x64 = 512 float4
            int p = tid + l * 256;
            int k = p >> 4;                       // 16 float4 per row
            int n4 = (p & 15) << 2;
            *(float4*)&Bs[k][n4] = *(const float4*)&W[(k0 + k) * 64 + n4];
        }
        __syncthreads();
#pragma unroll
        for (int kk = 0; kk < BK; kk++) {
            float a[4], b[4];
#pragma unroll
            for (int i = 0; i < 4; i++) a[i] = As[kk][ty * 4 + i];
#pragma unroll
            for (int j = 0; j < 4; j++) b[j] = Bs[kk][tx * 4 + j];
#pragma unroll
            for (int i = 0; i < 4; i++)
#pragma unroll
                for (int j = 0; j < 4; j++) acc[i][j] += a[i] * b[j];
        }
        __syncthreads();
    }
#pragma unroll
    for (int i = 0; i < 4; i++) {
        int m = bm + ty * 4 + i;
        if (m < NN) {
            float4 v = make_float4(acc[i][0], acc[i][1], acc[i][2], acc[i][3]);
            *(float4*)&g_xh[(size_t)m * HID + tx * 4] = v;
        }
    }
}

// per (node, head): attention scores s_i, s_j
__global__ void k_scores(const float* __restrict__ att) {
    int t = blockIdx.x * blockDim.x + threadIdx.x;
    if (t >= NN * HH) return;
    int n = t >> 3, h = t & 7;
    const float* xr = &g_xh[(size_t)n * HID + h * C1];
    float si = 0.f, sj = 0.f;
#pragma unroll
    for (int c = 0; c < C1; c++) {
        float v = xr[c];
        si += v * att[h * 16 + c];
        sj += v * att[h * 16 + 8 + c];
    }
    g_si[t] = si;
    g_sj[t] = sj;
}

// per edge: degree atomics + per-head attn max
__global__ void k_edge_deg_max(const int* __restrict__ row, const int* __restrict__ col,
                               const float* __restrict__ hw) {
    int e = blockIdx.x * blockDim.x + threadIdx.x;
    if (e >= EE) return;
    int r = row[e], c = col[e];
    atomicAdd(&g_D[r], hw[c]);
    atomicAdd(&g_B[c], 1.0f);
    const float* si = &g_si[r * HH];
    const float* sj = &g_sj[c * HH];
#pragma unroll
    for (int h = 0; h < HH; h++) {
        float a = lrelu(si[h] + sj[h]);
        atomicMax(&g_amax[r * HH + h], f2u_mono(a));
    }
}

__global__ void k_finalize_deg(const float* __restrict__ hw) {
    int n = blockIdx.x * blockDim.x + threadIdx.x;
    if (n >= NN) return;
    float D = g_D[n];
    g_Dinv[n] = D > 0.f ? 1.0f / D : 0.f;
    float B = g_B[n];
    g_Binv[n] = B > 0.f ? hw[n] / B : 0.f;
}

// per edge: ex = exp(a - amax), store, accumulate denominator
__global__ void k_edge_den(const int* __restrict__ row, const int* __restrict__ col) {
    int e = blockIdx.x * blockDim.x + threadIdx.x;
    if (e >= EE) return;
    int r = row[e], c = col[e];
    const float* si = &g_si[r * HH];
    const float* sj = &g_sj[c * HH];
    float ex[HH];
#pragma unroll
    for (int h = 0; h < HH; h++) {
        float a = lrelu(si[h] + sj[h]);
        float m = u2f_mono(g_amax[r * HH + h]);
        ex[h] = __expf(a - m);
        atomicAdd(&g_den[r * HH + h], ex[h]);
    }
    float4* dst = (float4*)&g_alpha[(size_t)e * HH];
    dst[0] = make_float4(ex[0], ex[1], ex[2], ex[3]);
    dst[1] = make_float4(ex[4], ex[5], ex[6], ex[7]);
}

// per (edge, head): finalize alpha; propagate nodes -> hyperedges
__global__ void k_prop1(const int* __restrict__ row, const int* __restrict__ col) {
    int t = blockIdx.x * blockDim.x + threadIdx.x;
    if (t >= EE * HH) return;
    int e = t >> 3, h = t & 7;
    int r = row[e], c = col[e];
    float ex = g_alpha[t];
    float al = ex / (g_den[r * HH + h] + 1e-16f);
    g_alpha[t] = al;
    float s = al * g_Binv[c];
    const float* src = &g_xh[((size_t)r << 6) + (h << 3)];
    float* dst = &g_oute[((size_t)c << 6) + (h << 3)];
    float4 v0 = *(const float4*)(src);
    float4 v1 = *(const float4*)(src + 4);
    atomicAdd(dst + 0, v0.x * s); atomicAdd(dst + 1, v0.y * s);
    atomicAdd(dst + 2, v0.z * s); atomicAdd(dst + 3, v0.w * s);
    atomicAdd(dst + 4, v1.x * s); atomicAdd(dst + 5, v1.y * s);
    atomicAdd(dst + 6, v1.z * s); atomicAdd(dst + 7, v1.w * s);
}

// per (edge, head): propagate hyperedges -> nodes
__global__ void k_prop2(const int* __restrict__ row, const int* __restrict__ col) {
    int t = blockIdx.x * blockDim.x + threadIdx.x;
    if (t >= EE * HH) return;
    int e = t >> 3, h = t & 7;
    int r = row[e], c = col[e];
    float s = g_alpha[t] * g_Dinv[r];
    const float* src = &g_oute[((size_t)c << 6) + (h << 3)];
    float* dst = &g_h1[((size_t)r << 6) + (h << 3)];
    float4 v0 = *(const float4*)(src);
    float4 v1 = *(const float4*)(src + 4);
    atomicAdd(dst + 0, v0.x * s); atomicAdd(dst + 1, v0.y * s);
    atomicAdd(dst + 2, v0.z * s); atomicAdd(dst + 3, v0.w * s);
    atomicAdd(dst + 4, v1.x * s); atomicAdd(dst + 5, v1.y * s);
    atomicAdd(dst + 6, v1.z * s); atomicAdd(dst + 7, v1.w * s);
}

__global__ void k_elu(const float* __restrict__ b1) {
    int t = blockIdx.x * blockDim.x + threadIdx.x;
    if (t >= NN * HID) return;
    float v = g_h1[t] + b1[t & 63];
    g_h1[t] = v > 0.f ? v : expm1f(v);
}

// g_xh2[N,8(pad)] = h1[N,64] @ W2[64,7]
__global__ void k_gemm2(const float* __restrict__ W2) {
    int t = blockIdx.x * blockDim.x + threadIdx.x;
    if (t >= NN * 8) return;
    int n = t >> 3, j = t & 7;
    if (j >= NCLS) { g_xh2[t] = 0.f; return; }
    const float* hr = &g_h1[(size_t)n * HID];
    float acc = 0.f;
#pragma unroll
    for (int k = 0; k < HID; k++) acc += hr[k] * W2[k * NCLS + j];
    g_xh2[t] = acc;
}

__global__ void k2_prop1(const int* __restrict__ row, const int* __restrict__ col) {
    int t = blockIdx.x * blockDim.x + threadIdx.x;
    if (t >= EE * 8) return;
    int e = t >> 3, j = t & 7;
    if (j >= NCLS) return;
    int r = row[e], c = col[e];
    float v = g_xh2[(r << 3) + j] * g_Binv[c];
    atomicAdd(&g_oute2[(c << 3) + j], v);
}

__global__ void k2_prop2(const int* __restrict__ row, const int* __restrict__ col) {
    int t = blockIdx.x * blockDim.x + threadIdx.x;
    if (t >= EE * 8) return;
    int e = t >> 3, j = t & 7;
    if (j >= NCLS) return;
    int r = row[e], c = col[e];
    float v = g_oute2[(c << 3) + j] * g_Dinv[r];
    atomicAdd(&g_out2[(r << 3) + j], v);
}

__global__ void k_logsoftmax(const float* __restrict__ b2, float* __restrict__ out) {
    int n = blockIdx.x * blockDim.x + threadIdx.x;
    if (n >= NN) return;
    float v[NCLS];
    float mx = -1e30f;
#pragma unroll
    for (int j = 0; j < NCLS; j++) {
        v[j] = g_out2[(n << 3) + j] + b2[j];
        mx = fmaxf(mx, v[j]);
    }
    float s = 0.f;
#pragma unroll
    for (int j = 0; j < NCLS; j++) s += __expf(v[j] - mx);
    float ls = logf(s);
#pragma unroll
    for (int j = 0; j < NCLS; j++) out[n * NCLS + j] = v[j] - mx - ls;
}

// ---------------- launch ------------------------------------------------------

extern "C" void kernel_launch(void* const* d_in, const int* in_sizes, int n_in,
                              void* d_out, int out_size) {
    const float* x   = (const float*)d_in[0];
    const int*   ei  = (const int*)  d_in[1];
    const float* hw  = (const float*)d_in[2];
    const float* W1  = (const float*)d_in[3];
    const float* att = (const float*)d_in[4];
    const float* b1  = (const float*)d_in[5];
    const float* W2  = (const float*)d_in[6];
    const float* b2  = (const float*)d_in[7];
    float* out = (float*)d_out;

    const int* row = ei;        // edge_index[0]
    const int* col = ei + EE;   // edge_index[1]

    k_init<<<2048, 256>>>();
    k_gemm1<<<(NN + BM - 1) / BM, 256>>>(x, W1);
    k_scores<<<(NN * HH + 255) / 256, 256>>>(att);
    k_edge_deg_max<<<(EE + 255) / 256, 256>>>(row, col, hw);
    k_finalize_deg<<<(NN + 255) / 256, 256>>>(hw);
    k_edge_den<<<(EE + 255) / 256, 256>>>(row, col);
    k_prop1<<<(EE * HH + 255) / 256, 256>>>(row, col);
    k_prop2<<<(EE * HH + 255) / 256, 256>>>(row, col);
    k_elu<<<(NN * HID + 255) / 256, 256>>>(b1);
    k_gemm2<<<(NN * 8 + 255) / 256, 256>>>(W2);
    k2_prop1<<<(EE * 8 + 255) / 256, 256>>>(row, col);
    k2_prop2<<<(EE * 8 + 255) / 256, 256>>>(row, col);
    k_logsoftmax<<<(NN + 255) / 256, 256>>>(b2, out);
}

// round 2
// speedup vs baseline: 2.6235x; 2.6235x over previous
#include <cuda_runtime.h>
#include <math.h>

#define NN   50000
#define EE   1600000
#define FIN  512
#define HH   8
#define C1   8
#define HID  64
#define NCLS 7
#define NEG_SLOPE 0.2f

// ---------------- scratch (device globals; no runtime allocation) ------------
__device__ float    g_xh   [NN * HID];   // x @ W1
__device__ float    g_si   [NN * HH];
__device__ float    g_sj   [NN * HH];
__device__ float    g_den  [NN * HH];
__device__ float    g_D    [NN];
__device__ float    g_B    [NN];
__device__ float    g_Dinv [NN];
__device__ float    g_Binv [NN];
__device__ float    g_oute [NN * HID];   // hyperedge accumulator, layer 1
__device__ float    g_h1   [NN * HID];   // node output layer 1 (then elu'd)
__device__ float    g_alpha[EE * HH];    // per-edge attention (ex, then alpha)
__device__ float    g_xh2  [NN * 8];     // h @ W2, padded 7->8
__device__ float    g_oute2[NN * 8];
__device__ float    g_out2 [NN * 8];

__device__ __forceinline__ float lrelu(float a) {
    return a > 0.f ? a : NEG_SLOPE * a;
}

// vectorized global reduction (sm_90+)
__device__ __forceinline__ void red4(float* p, float a, float b, float c, float d) {
    asm volatile("red.global.add.v4.f32 [%0], {%1,%2,%3,%4};"
                 :: "l"(p), "f"(a), "f"(b), "f"(c), "f"(d) : "memory");
}

// ---------------- kernels ----------------------------------------------------

__global__ void k_init() {
    int i = blockIdx.x * blockDim.x + threadIdx.x;
    int stride = gridDim.x * blockDim.x;
    for (int t = i; t < NN; t += stride) { g_D[t] = 0.f; g_B[t] = 0.f; }
    for (int t = i; t < NN * HH; t += stride) {
        g_den[t] = 0.f; g_oute2[t] = 0.f; g_out2[t] = 0.f;
    }
    for (int t = i; t < NN * HID; t += stride) { g_oute[t] = 0.f; g_h1[t] = 0.f; }
}

// tiled fp32 GEMM: g_xh[N,64] = X[N,512] @ W1[512,64]
#define BM 64
#define BK 32
__global__ void k_gemm1(const float* __restrict__ X, const float* __restrict__ W) {
    __shared__ float As[BK][BM + 1];
    __shared__ float Bs[BK][64];
    int bm = blockIdx.x * BM;
    int tid = threadIdx.x;                 // 256 threads
    int tx = tid & 15, ty = tid >> 4;      // 16x16
    float acc[4][4];
#pragma unroll
    for (int i = 0; i < 4; i++)
#pragma unroll
        for (int j = 0; j < 4; j++) acc[i][j] = 0.f;

    for (int k0 = 0; k0 < FIN; k0 += BK) {
#pragma unroll
        for (int l = 0; l < 2; l++) {            // A tile: 64x32 = 512 float4
            int p = tid + l * 256;
            int m = p >> 3;
            int k4 = (p & 7) << 2;
            float4 v = make_float4(0.f, 0.f, 0.f, 0.f);
            if (bm + m < NN) v = *(const float4*)&X[(size_t)(bm + m) * FIN + k0 + k4];
            As[k4 + 0][m] = v.x; As[k4 + 1][m] = v.y;
            As[k4 + 2][m] = v.z; As[k4 + 3][m] = v.w;
        }
#pragma unroll
        for (int l = 0; l < 2; l++) {            // B tile: 32x64 = 512 float4
            int p = tid + l * 256;
            int k = p >> 4;
            int n4 = (p & 15) << 2;
            *(float4*)&Bs[k][n4] = *(const float4*)&W[(k0 + k) * 64 + n4];
        }
        __syncthreads();
#pragma unroll
        for (int kk = 0; kk < BK; kk++) {
            float a[4], b[4];
#pragma unroll
            for (int i = 0; i < 4; i++) a[i] = As[kk][ty * 4 + i];
#pragma unroll
            for (int j = 0; j < 4; j++) b[j] = Bs[kk][tx * 4 + j];
#pragma unroll
            for (int i = 0; i < 4; i++)
#pragma unroll
                for (int j = 0; j < 4; j++) acc[i][j] += a[i] * b[j];
        }
        __syncthreads();
    }
#pragma unroll
    for (int i = 0; i < 4; i++) {
        int m = bm + ty * 4 + i;
        if (m < NN) {
            float4 v = make_float4(acc[i][0], acc[i][1], acc[i][2], acc[i][3]);
            *(float4*)&g_xh[(size_t)m * HID + tx * 4] = v;
        }
    }
}

// per (node, head): attention scores s_i, s_j
__global__ void k_scores(const float* __restrict__ att) {
    int t = blockIdx.x * blockDim.x + threadIdx.x;
    if (t >= NN * HH) return;
    int n = t >> 3, h = t & 7;
    const float* xr = &g_xh[(size_t)n * HID + h * C1];
    float si = 0.f, sj = 0.f;
#pragma unroll
    for (int c = 0; c < C1; c++) {
        float v = xr[c];
        si += v * att[h * 16 + c];
        sj += v * att[h * 16 + 8 + c];
    }
    g_si[t] = si;
    g_sj[t] = sj;
}

// single fused edge pass: degrees + softmax numerator (exp, no max needed:
// softmax is shift-invariant and scores are O(1), no overflow risk)
__global__ void k_edge1(const int* __restrict__ row, const int* __restrict__ col,
                        const float* __restrict__ hw) {
    int e = blockIdx.x * blockDim.x + threadIdx.x;
    if (e >= EE) return;
    int r = row[e], c = col[e];
    atomicAdd(&g_D[r], __ldg(&hw[c]));
    atomicAdd(&g_B[c], 1.0f);
    const float4* si = (const float4*)&g_si[r * HH];
    const float4* sj = (const float4*)&g_sj[c * HH];
    float4 si0 = si[0], si1 = si[1];
    float4 sj0 = sj[0], sj1 = sj[1];
    float ex[HH];
    ex[0] = __expf(lrelu(si0.x + sj0.x));
    ex[1] = __expf(lrelu(si0.y + sj0.y));
    ex[2] = __expf(lrelu(si0.z + sj0.z));
    ex[3] = __expf(lrelu(si0.w + sj0.w));
    ex[4] = __expf(lrelu(si1.x + sj1.x));
    ex[5] = __expf(lrelu(si1.y + sj1.y));
    ex[6] = __expf(lrelu(si1.z + sj1.z));
    ex[7] = __expf(lrelu(si1.w + sj1.w));
    float4* dst = (float4*)&g_alpha[(size_t)e * HH];
    dst[0] = make_float4(ex[0], ex[1], ex[2], ex[3]);
    dst[1] = make_float4(ex[4], ex[5], ex[6], ex[7]);
    red4(&g_den[r * HH + 0], ex[0], ex[1], ex[2], ex[3]);
    red4(&g_den[r * HH + 4], ex[4], ex[5], ex[6], ex[7]);
}

__global__ void k_finalize_deg(const float* __restrict__ hw) {
    int n = blockIdx.x * blockDim.x + threadIdx.x;
    if (n >= NN) return;
    float D = g_D[n];
    g_Dinv[n] = D > 0.f ? 1.0f / D : 0.f;
    float B = g_B[n];
    g_Binv[n] = B > 0.f ? hw[n] / B : 0.f;
}

// per (edge, head): finalize alpha; propagate nodes -> hyperedges (v4 RED)
__global__ void k_prop1(const int* __restrict__ row, const int* __restrict__ col) {
    int t = blockIdx.x * blockDim.x + threadIdx.x;
    if (t >= EE * HH) return;
    int e = t >> 3, h = t & 7;
    int r = row[e], c = col[e];
    float ex = g_alpha[t];
    float al = ex / (g_den[r * HH + h] + 1e-16f);
    g_alpha[t] = al;
    float s = al * __ldg(&g_Binv[c]);
    const float4* src = (const float4*)&g_xh[((size_t)r << 6) + (h << 3)];
    float4 v0 = src[0], v1 = src[1];
    float* dst = &g_oute[((size_t)c << 6) + (h << 3)];
    red4(dst + 0, v0.x * s, v0.y * s, v0.z * s, v0.w * s);
    red4(dst + 4, v1.x * s, v1.y * s, v1.z * s, v1.w * s);
}

// per (edge, head): propagate hyperedges -> nodes (v4 RED)
__global__ void k_prop2(const int* __restrict__ row, const int* __restrict__ col) {
    int t = blockIdx.x * blockDim.x + threadIdx.x;
    if (t >= EE * HH) return;
    int e = t >> 3, h = t & 7;
    int r = row[e], c = col[e];
    float s = g_alpha[t] * __ldg(&g_Dinv[r]);
    const float4* src = (const float4*)&g_oute[((size_t)c << 6) + (h << 3)];
    float4 v0 = src[0], v1 = src[1];
    float* dst = &g_h1[((size_t)r << 6) + (h << 3)];
    red4(dst + 0, v0.x * s, v0.y * s, v0.z * s, v0.w * s);
    red4(dst + 4, v1.x * s, v1.y * s, v1.z * s, v1.w * s);
}

__global__ void k_elu(const float* __restrict__ b1) {
    int t = blockIdx.x * blockDim.x + threadIdx.x;
    if (t >= NN * HID) return;
    float v = g_h1[t] + b1[t & 63];
    g_h1[t] = v > 0.f ? v : expm1f(v);
}

// g_xh2[N,8(pad)] = h1[N,64] @ W2[64,7]
__global__ void k_gemm2(const float* __restrict__ W2) {
    int t = blockIdx.x * blockDim.x + threadIdx.x;
    if (t >= NN * 8) return;
    int n = t >> 3, j = t & 7;
    if (j >= NCLS) { g_xh2[t] = 0.f; return; }
    const float* hr = &g_h1[(size_t)n * HID];
    float acc = 0.f;
#pragma unroll
    for (int k = 0; k < HID; k++) acc += hr[k] * W2[k * NCLS + j];
    g_xh2[t] = acc;
}

// layer-2 propagate, per edge (padded class 7 is zero)
__global__ void k2_prop1(const int* __restrict__ row, const int* __restrict__ col) {
    int e = blockIdx.x * blockDim.x + threadIdx.x;
    if (e >= EE) return;
    int r = row[e], c = col[e];
    float s = __ldg(&g_Binv[c]);
    const float4* src = (const float4*)&g_xh2[r << 3];
    float4 v0 = src[0], v1 = src[1];
    float* dst = &g_oute2[c << 3];
    red4(dst + 0, v0.x * s, v0.y * s, v0.z * s, v0.w * s);
    red4(dst + 4, v1.x * s, v1.y * s, v1.z * s, 0.f);
}

__global__ void k2_prop2(const int* __restrict__ row, const int* __restrict__ col) {
    int e = blockIdx.x * blockDim.x + threadIdx.x;
    if (e >= EE) return;
    int r = row[e], c = col[e];
    float s = __ldg(&g_Dinv[r]);
    const float4* src = (const float4*)&g_oute2[c << 3];
    float4 v0 = src[0], v1 = src[1];
    float* dst = &g_out2[r << 3];
    red4(dst + 0, v0.x * s, v0.y * s, v0.z * s, v0.w * s);
    red4(dst + 4, v1.x * s, v1.y * s, v1.z * s, 0.f);
}

__global__ void k_logsoftmax(const float* __restrict__ b2, float* __restrict__ out) {
    int n = blockIdx.x * blockDim.x + threadIdx.x;
    if (n >= NN) return;
    float v[NCLS];
    float mx = -1e30f;
#pragma unroll
    for (int j = 0; j < NCLS; j++) {
        v[j] = g_out2[(n << 3) + j] + b2[j];
        mx = fmaxf(mx, v[j]);
    }
    float s = 0.f;
#pragma unroll
    for (int j = 0; j < NCLS; j++) s += __expf(v[j] - mx);
    float ls = logf(s);
#pragma unroll
    for (int j = 0; j < NCLS; j++) out[n * NCLS + j] = v[j] - mx - ls;
}

// ---------------- launch ------------------------------------------------------

extern "C" void kernel_launch(void* const* d_in, const int* in_sizes, int n_in,
                              void* d_out, int out_size) {
    const float* x   = (const float*)d_in[0];
    const int*   ei  = (const int*)  d_in[1];
    const float* hw  = (const float*)d_in[2];
    const float* W1  = (const float*)d_in[3];
    const float* att = (const float*)d_in[4];
    const float* b1  = (const float*)d_in[5];
    const float* W2  = (const float*)d_in[6];
    const float* b2  = (const float*)d_in[7];
    float* out = (float*)d_out;

    const int* row = ei;        // edge_index[0]
    const int* col = ei + EE;   // edge_index[1]

    k_init<<<2048, 256>>>();
    k_gemm1<<<(NN + BM - 1) / BM, 256>>>(x, W1);
    k_scores<<<(NN * HH + 255) / 256, 256>>>(att);
    k_edge1<<<(EE + 255) / 256, 256>>>(row, col, hw);
    k_finalize_deg<<<(NN + 255) / 256, 256>>>(hw);
    k_prop1<<<(EE * HH + 255) / 256, 256>>>(row, col);
    k_prop2<<<(EE * HH + 255) / 256, 256>>>(row, col);
    k_elu<<<(NN * HID + 255) / 256, 256>>>(b1);
    k_gemm2<<<(NN * 8 + 255) / 256, 256>>>(W2);
    k2_prop1<<<(EE + 255) / 256, 256>>>(row, col);
    k2_prop2<<<(EE + 255) / 256, 256>>>(row, col);
    k_logsoftmax<<<(NN + 255) / 256, 256>>>(b2, out);
}

// round 4
// speedup vs baseline: 2.7251x; 1.0387x over previous
#include <cuda_runtime.h>
#include <mma.h>
#include <math.h>

using namespace nvcuda;

#define NN   50000
#define EE   1600000
#define FIN  512
#define HH   8
#define HID  64
#define NCLS 7
#define NEG_SLOPE 0.2f
#define NB   196            // (NN+255)/256

// ---------------- scratch (device globals) -----------------------------------
__device__ int   g_cntR[NN], g_cntC[NN];
__device__ int   g_offR[NN + 1], g_offC[NN + 1];
__device__ int   g_curR[NN], g_curC[NN];
__device__ int   g_bsumR[256], g_bsumC[256], g_bprefR[256], g_bprefC[256];
__device__ int   g_sortedR[EE];   // edges sorted by col: stores row id
__device__ int   g_sortedC[EE];   // edges sorted by row: stores col id
__device__ float g_xh  [NN * HID];
__device__ float g_si  [NN * HH];
__device__ float g_sj  [NN * HH];
__device__ float g_rden[NN * HH];
__device__ float g_Dinv[NN];
__device__ float g_Binv[NN];
__device__ float g_oute[NN * HID];
__device__ float g_h1  [NN * HID];
__device__ float g_xh2 [NN * 8];
__device__ float g_oute2[NN * 8];
__device__ float g_out2 [NN * 8];

__device__ __forceinline__ float lrelu(float a) { return a > 0.f ? a : NEG_SLOPE * a; }
// round-to-nearest tf32; result bits are a valid fp32 (truncated mantissa)
__device__ __forceinline__ float tf32r(float x) {
    unsigned r; asm("cvt.rna.tf32.f32 %0, %1;" : "=r"(r) : "f"(x));
    return __uint_as_float(r);
}

// ---------------- sort construction ------------------------------------------

__global__ void k_init() {
    int i = blockIdx.x * blockDim.x + threadIdx.x;
    if (i < NN) { g_cntR[i] = 0; g_cntC[i] = 0; }
    if (i == 0) { g_offR[NN] = EE; g_offC[NN] = EE; }
}

__global__ void k_count(const int* __restrict__ row, const int* __restrict__ col) {
    int e = blockIdx.x * blockDim.x + threadIdx.x;
    if (e >= EE) return;
    atomicAdd(&g_cntR[row[e]], 1);
    atomicAdd(&g_cntC[col[e]], 1);
}

__global__ void k_bsum() {
    int t = threadIdx.x, b = blockIdx.x;
    int i = b * 256 + t;
    int vr = (i < NN) ? g_cntR[i] : 0;
    int vc = (i < NN) ? g_cntC[i] : 0;
    __shared__ int sr[8], sc[8];
#pragma unroll
    for (int o = 16; o; o >>= 1) {
        vr += __shfl_down_sync(~0u, vr, o);
        vc += __shfl_down_sync(~0u, vc, o);
    }
    if ((t & 31) == 0) { sr[t >> 5] = vr; sc[t >> 5] = vc; }
    __syncthreads();
    if (t < 8) {
        vr = sr[t]; vc = sc[t];
#pragma unroll
        for (int o = 4; o; o >>= 1) {
            vr += __shfl_down_sync(0xffu, vr, o);
            vc += __shfl_down_sync(0xffu, vc, o);
        }
        if (t == 0) { g_bsumR[b] = vr; g_bsumC[b] = vc; }
    }
}

__global__ void k_scanb() {
    __shared__ int s[256];
    int t = threadIdx.x;
    int v = (t < NB) ? g_bsumR[t] : 0;
    s[t] = v; __syncthreads();
    for (int d = 1; d < 256; d <<= 1) {
        int x = (t >= d) ? s[t - d] : 0; __syncthreads();
        s[t] += x; __syncthreads();
    }
    g_bprefR[t] = s[t] - v;
    __syncthreads();
    int vc = (t < NB) ? g_bsumC[t] : 0;
    s[t] = vc; __syncthreads();
    for (int d = 1; d < 256; d <<= 1) {
        int x = (t >= d) ? s[t - d] : 0; __syncthreads();
        s[t] += x; __syncthreads();
    }
    g_bprefC[t] = s[t] - vc;
}

__global__ void k_scanfin(const float* __restrict__ hw) {
    __shared__ int s[256];
    int t = threadIdx.x, b = blockIdx.x;
    int i = b * 256 + t;
    int v = (i < NN) ? g_cntR[i] : 0;
    s[t] = v; __syncthreads();
    for (int d = 1; d < 256; d <<= 1) {
        int x = (t >= d) ? s[t - d] : 0; __syncthreads();
        s[t] += x; __syncthreads();
    }
    if (i < NN) {
        int off = g_bprefR[b] + s[t] - v;
        g_offR[i] = off; g_curR[i] = off;
    }
    __syncthreads();
    int vc = (i < NN) ? g_cntC[i] : 0;
    s[t] = vc; __syncthreads();
    for (int d = 1; d < 256; d <<= 1) {
        int x = (t >= d) ? s[t - d] : 0; __syncthreads();
        s[t] += x; __syncthreads();
    }
    if (i < NN) {
        int off = g_bprefC[b] + s[t] - vc;
        g_offC[i] = off; g_curC[i] = off;
        g_Binv[i] = vc > 0 ? __ldg(&hw[i]) / (float)vc : 0.f;
    }
}

__global__ void k_scatter(const int* __restrict__ row, const int* __restrict__ col) {
    int e = blockIdx.x * blockDim.x + threadIdx.x;
    if (e >= EE) return;
    int r = row[e], c = col[e];
    int pc = atomicAdd(&g_curC[c], 1);
    g_sortedR[pc] = r;
    int pr = atomicAdd(&g_curR[r], 1);
    g_sortedC[pr] = c;
}

// ---------------- GEMM1: tf32 tensor cores, 3-term split ----------------------
// g_xh[N,64] = X[N,512] @ W1[512,64]
#define GM_BM 128
#define GM_BK 32
__global__ void k_gemm1(const float* __restrict__ X, const float* __restrict__ W) {
    __shared__ float smem[12288];            // 48KB
    float* sAhi = smem;                      // 128*32
    float* sAlo = smem + 4096;               // 128*32
    float* sBhi = smem + 8192;               // 32*64
    float* sBlo = smem + 10240;              // 32*64

    int tid = threadIdx.x;
    int warp = tid >> 5;
    int wm = warp >> 1;       // 0..3  (32 rows each)
    int wn = warp & 1;        // 0..1  (32 cols each)
    int bm = blockIdx.x * GM_BM;

    wmma::fragment<wmma::accumulator, 16, 16, 8, float> acc[2][2];
#pragma unroll
    for (int i = 0; i < 2; i++)
#pragma unroll
        for (int j = 0; j < 2; j++) wmma::fill_fragment(acc[i][j], 0.f);

    for (int k0 = 0; k0 < FIN; k0 += GM_BK) {
#pragma unroll
        for (int l = 0; l < 4; l++) {        // A tile: 128x32 = 1024 float4
            int p = tid + l * 256;
            int m = p >> 3;
            int k4 = (p & 7) << 2;
            float4 v = make_float4(0.f, 0.f, 0.f, 0.f);
            if (bm + m < NN) v = *(const float4*)&X[(size_t)(bm + m) * FIN + k0 + k4];
            float h0 = tf32r(v.x), h1 = tf32r(v.y), h2 = tf32r(v.z), h3 = tf32r(v.w);
            float* hi = &sAhi[m * GM_BK + k4];
            float* lo = &sAlo[m * GM_BK + k4];
            hi[0] = h0; hi[1] = h1; hi[2] = h2; hi[3] = h3;
            lo[0] = tf32r(v.x - h0); lo[1] = tf32r(v.y - h1);
            lo[2] = tf32r(v.z - h2); lo[3] = tf32r(v.w - h3);
        }
#pragma unroll
        for (int l = 0; l < 2; l++) {        // B tile: 32x64 = 512 float4
            int p = tid + l * 256;
            int k = p >> 4;
            int n4 = (p & 15) << 2;
            float4 v = *(const float4*)&W[(size_t)(k0 + k) * 64 + n4];
            float h0 = tf32r(v.x), h1 = tf32r(v.y), h2 = tf32r(v.z), h3 = tf32r(v.w);
            float* hi = &sBhi[k * 64 + n4];
            float* lo = &sBlo[k * 64 + n4];
            hi[0] = h0; hi[1] = h1; hi[2] = h2; hi[3] = h3;
            lo[0] = tf32r(v.x - h0); lo[1] = tf32r(v.y - h1);
            lo[2] = tf32r(v.z - h2); lo[3] = tf32r(v.w - h3);
        }
        __syncthreads();
#pragma unroll
        for (int kk = 0; kk < GM_BK; kk += 8) {
            wmma::fragment<wmma::matrix_a, 16, 16, 8, wmma::precision::tf32, wmma::row_major> aHi[2], aLo[2];
            wmma::fragment<wmma::matrix_b, 16, 16, 8, wmma::precision::tf32, wmma::row_major> bHi[2], bLo[2];
#pragma unroll
            for (int i = 0; i < 2; i++) {
                wmma::load_matrix_sync(aHi[i], &sAhi[(wm * 32 + i * 16) * GM_BK + kk], GM_BK);
                wmma::load_matrix_sync(aLo[i], &sAlo[(wm * 32 + i * 16) * GM_BK + kk], GM_BK);
            }
#pragma unroll
            for (int j = 0; j < 2; j++) {
                wmma::load_matrix_sync(bHi[j], &sBhi[kk * 64 + wn * 32 + j * 16], 64);
                wmma::load_matrix_sync(bLo[j], &sBlo[kk * 64 + wn * 32 + j * 16], 64);
            }
#pragma unroll
            for (int i = 0; i < 2; i++)
#pragma unroll
                for (int j = 0; j < 2; j++) {
                    wmma::mma_sync(acc[i][j], aHi[i], bHi[j], acc[i][j]);
                    wmma::mma_sync(acc[i][j], aHi[i], bLo[j], acc[i][j]);
                    wmma::mma_sync(acc[i][j], aLo[i], bHi[j], acc[i][j]);
                }
        }
        __syncthreads();
    }
    // epilogue: stage C through smem (reuse) for guarded store
    float* sC = smem;                        // 128*64 = 8192 floats
#pragma unroll
    for (int i = 0; i < 2; i++)
#pragma unroll
        for (int j = 0; j < 2; j++)
            wmma::store_matrix_sync(&sC[(wm * 32 + i * 16) * 64 + wn * 32 + j * 16],
                                    acc[i][j], 64, wmma::mem_row_major);
    __syncthreads();
#pragma unroll
    for (int l = 0; l < 8; l++) {
        int p = tid + l * 256;               // float4 index, 2048 total
        int m = p >> 4;
        int n4 = (p & 15) << 2;
        if (bm + m < NN)
            *(float4*)&g_xh[(size_t)(bm + m) * 64 + n4] = *(float4*)&sC[m * 64 + n4];
    }
}

// ---------------- attention scores -------------------------------------------
__global__ void k_scores(const float* __restrict__ att) {
    int t = blockIdx.x * blockDim.x + threadIdx.x;
    if (t >= NN * HH) return;
    int n = t >> 3, h = t & 7;
    const float* xr = &g_xh[(size_t)n * HID + h * 8];
    float si = 0.f, sj = 0.f;
#pragma unroll
    for (int c = 0; c < 8; c++) {
        float v = xr[c];
        si += v * __ldg(&att[h * 16 + c]);
        sj += v * __ldg(&att[h * 16 + 8 + c]);
    }
    g_si[t] = si;
    g_sj[t] = sj;
}

// ---------------- denominator + Dinv (warp per node, by-row CSR) --------------
__global__ void k_den(const float* __restrict__ hw) {
    int w = (blockIdx.x * blockDim.x + threadIdx.x) >> 5;
    if (w >= NN) return;
    int lane = threadIdx.x & 31;
    int g = lane >> 3, h = lane & 7;
    int start = g_offR[w], end = g_offR[w + 1];
    float si_h = g_si[w * 8 + h];
    float den = 0.f, Dacc = 0.f;
    for (int i = start + g; i < end; i += 4) {
        int c = g_sortedC[i];
        float sj = __ldg(&g_sj[c * 8 + h]);
        den += __expf(lrelu(si_h + sj));
        if (h == 0) Dacc += __ldg(&hw[c]);
    }
    den += __shfl_xor_sync(~0u, den, 8);
    den += __shfl_xor_sync(~0u, den, 16);
    Dacc += __shfl_xor_sync(~0u, Dacc, 8);
    Dacc += __shfl_xor_sync(~0u, Dacc, 16);
    if (g == 0) g_rden[w * 8 + h] = 1.0f / (den + 1e-16f);
    if (lane == 0) g_Dinv[w] = Dacc > 0.f ? 1.0f / Dacc : 0.f;
}

// ---------------- prop1: nodes -> hyperedges (warp per hyperedge) -------------
__global__ void k_prop1() {
    int w = (blockIdx.x * blockDim.x + threadIdx.x) >> 5;
    if (w >= NN) return;
    int lane = threadIdx.x & 31;
    int h = lane >> 2;
    int start = g_offC[w], end = g_offC[w + 1];
    float sj_h = g_sj[w * 8 + h];
    float binv = g_Binv[w];
    float ax = 0.f, ay = 0.f;
    int i = start;
    int n2 = start + ((end - start) & ~1);
    for (; i < n2; i += 2) {
        int r0 = g_sortedR[i], r1 = g_sortedR[i + 1];
        float si0 = __ldg(&g_si[r0 * 8 + h]);
        float si1 = __ldg(&g_si[r1 * 8 + h]);
        float rd0 = __ldg(&g_rden[r0 * 8 + h]);
        float rd1 = __ldg(&g_rden[r1 * 8 + h]);
        float2 f0 = *(const float2*)&g_xh[(size_t)r0 * 64 + lane * 2];
        float2 f1 = *(const float2*)&g_xh[(size_t)r1 * 64 + lane * 2];
        float w0 = __expf(lrelu(si0 + sj_h)) * rd0;
        float w1 = __expf(lrelu(si1 + sj_h)) * rd1;
        ax += w0 * f0.x + w1 * f1.x;
        ay += w0 * f0.y + w1 * f1.y;
    }
    if (i < end) {
        int r0 = g_sortedR[i];
        float si0 = __ldg(&g_si[r0 * 8 + h]);
        float rd0 = __ldg(&g_rden[r0 * 8 + h]);
        float2 f0 = *(const float2*)&g_xh[(size_t)r0 * 64 + lane * 2];
        float w0 = __expf(lrelu(si0 + sj_h)) * rd0;
        ax += w0 * f0.x; ay += w0 * f0.y;
    }
    float2 o = make_float2(ax * binv, ay * binv);
    *(float2*)&g_oute[(size_t)w * 64 + lane * 2] = o;
}

// ---------------- prop2: hyperedges -> nodes, + bias + ELU --------------------
__global__ void k_prop2(const float* __restrict__ b1) {
    int w = (blockIdx.x * blockDim.x + threadIdx.x) >> 5;
    if (w >= NN) return;
    int lane = threadIdx.x & 31;
    int h = lane >> 2;
    int start = g_offR[w], end = g_offR[w + 1];
    float si_h = g_si[w * 8 + h];
    float rd_h = g_rden[w * 8 + h];
    float dinv = g_Dinv[w];
    float ax = 0.f, ay = 0.f;
    int i = start;
    int n2 = start + ((end - start) & ~1);
    for (; i < n2; i += 2) {
        int c0 = g_sortedC[i], c1 = g_sortedC[i + 1];
        float sj0 = __ldg(&g_sj[c0 * 8 + h]);
        float sj1 = __ldg(&g_sj[c1 * 8 + h]);
        float2 f0 = *(const float2*)&g_oute[(size_t)c0 * 64 + lane * 2];
        float2 f1 = *(const float2*)&g_oute[(size_t)c1 * 64 + lane * 2];
        float w0 = __expf(lrelu(si_h + sj0)) * rd_h;
        float w1 = __expf(lrelu(si_h + sj1)) * rd_h;
        ax += w0 * f0.x + w1 * f1.x;
        ay += w0 * f0.y + w1 * f1.y;
    }
    if (i < end) {
        int c0 = g_sortedC[i];
        float sj0 = __ldg(&g_sj[c0 * 8 + h]);
        float2 f0 = *(const float2*)&g_oute[(size_t)c0 * 64 + lane * 2];
        float w0 = __expf(lrelu(si_h + sj0)) * rd_h;
        ax += w0 * f0.x; ay += w0 * f0.y;
    }
    float vx = ax * dinv + __ldg(&b1[lane * 2]);
    float vy = ay * dinv + __ldg(&b1[lane * 2 + 1]);
    vx = vx > 0.f ? vx : expm1f(vx);
    vy = vy > 0.f ? vy : expm1f(vy);
    *(float2*)&g_h1[(size_t)w * 64 + lane * 2] = make_float2(vx, vy);
}

// ---------------- gemm2: xh2[N,8(pad)] = h1[N,64] @ W2[64,7] ------------------
__global__ void k_gemm2(const float* __restrict__ W2) {
    __shared__ float sW[448];
    int tid = threadIdx.x;
    for (int i = tid; i < 448; i += 256) sW[i] = W2[i];
    __syncthreads();
    int n = blockIdx.x * 256 + tid;
    if (n >= NN) return;
    float acc[7];
#pragma unroll
    for (int j = 0; j < 7; j++) acc[j] = 0.f;
    const float4* hr = (const float4*)&g_h1[(size_t)n * 64];
#pragma unroll
    for (int k4 = 0; k4 < 16; k4++) {
        float4 hv = hr[k4];
#pragma unroll
        for (int j = 0; j < 7; j++)
            acc[j] += hv.x * sW[(k4 * 4 + 0) * 7 + j] + hv.y * sW[(k4 * 4 + 1) * 7 + j]
                    + hv.z * sW[(k4 * 4 + 2) * 7 + j] + hv.w * sW[(k4 * 4 + 3) * 7 + j];
    }
    float4* o = (float4*)&g_xh2[n * 8];
    o[0] = make_float4(acc[0], acc[1], acc[2], acc[3]);
    o[1] = make_float4(acc[4], acc[5], acc[6], 0.f);
}

// ---------------- layer-2 propagation (warp per segment) ----------------------
__global__ void k2_prop1() {
    int w = (blockIdx.x * blockDim.x + threadIdx.x) >> 5;
    if (w >= NN) return;
    int lane = threadIdx.x & 31;
    int g = lane >> 3, j = lane & 7;
    int start = g_offC[w], end = g_offC[w + 1];
    float acc = 0.f;
    for (int i = start + g; i < end; i += 4) {
        int r = g_sortedR[i];
        acc += __ldg(&g_xh2[r * 8 + j]);
    }
    acc += __shfl_xor_sync(~0u, acc, 8);
    acc += __shfl_xor_sync(~0u, acc, 16);
    if (g == 0) g_oute2[w * 8 + j] = acc * g_Binv[w];
}

__global__ void k2_prop2() {
    int w = (blockIdx.x * blockDim.x + threadIdx.x) >> 5;
    if (w >= NN) return;
    int lane = threadIdx.x & 31;
    int g = lane >> 3, j = lane & 7;
    int start = g_offR[w], end = g_offR[w + 1];
    float acc = 0.f;
    for (int i = start + g; i < end; i += 4) {
        int c = g_sortedC[i];
        acc += __ldg(&g_oute2[c * 8 + j]);
    }
    acc += __shfl_xor_sync(~0u, acc, 8);
    acc += __shfl_xor_sync(~0u, acc, 16);
    if (g == 0) g_out2[w * 8 + j] = acc * g_Dinv[w];
}

__global__ void k_logsoftmax(const float* __restrict__ b2, float* __restrict__ out) {
    int n = blockIdx.x * blockDim.x + threadIdx.x;
    if (n >= NN) return;
    float v[NCLS];
    float mx = -1e30f;
#pragma unroll
    for (int j = 0; j < NCLS; j++) {
        v[j] = g_out2[(n << 3) + j] + __ldg(&b2[j]);
        mx = fmaxf(mx, v[j]);
    }
    float s = 0.f;
#pragma unroll
    for (int j = 0; j < NCLS; j++) s += __expf(v[j] - mx);
    float ls = logf(s);
#pragma unroll
    for (int j = 0; j < NCLS; j++) out[n * NCLS + j] = v[j] - mx - ls;
}

// ---------------- launch ------------------------------------------------------

extern "C" void kernel_launch(void* const* d_in, const int* in_sizes, int n_in,
                              void* d_out, int out_size) {
    const float* x   = (const float*)d_in[0];
    const int*   ei  = (const int*)  d_in[1];
    const float* hw  = (const float*)d_in[2];
    const float* W1  = (const float*)d_in[3];
    const float* att = (const float*)d_in[4];
    const float* b1  = (const float*)d_in[5];
    const float* W2  = (const float*)d_in[6];
    const float* b2  = (const float*)d_in[7];
    float* out = (float*)d_out;

    const int* row = ei;        // edge_index[0]
    const int* col = ei + EE;   // edge_index[1]

    const int EB = (EE + 255) / 256;          // 6250
    const int WB = (NN * 32 + 255) / 256;     // 6250 (warp-per-segment kernels)

    k_init<<<NB, 256>>>();
    k_count<<<EB, 256>>>(row, col);
    k_bsum<<<NB, 256>>>();
    k_scanb<<<1, 256>>>();
    k_scanfin<<<NB, 256>>>(hw);
    k_scatter<<<EB, 256>>>(row, col);
    k_gemm1<<<(NN + GM_BM - 1) / GM_BM, 256>>>(x, W1);
    k_scores<<<(NN * HH + 255) / 256, 256>>>(att);
    k_den<<<WB, 256>>>(hw);
    k_prop1<<<WB, 256>>>();
    k_prop2<<<WB, 256>>>(b1);
    k_gemm2<<<NB, 256>>>(W2);
    k2_prop1<<<WB, 256>>>();
    k2_prop2<<<WB, 256>>>();
    k_logsoftmax<<<NB, 256>>>(b2, out);
}

// round 5
// speedup vs baseline: 2.8093x; 1.0309x over previous
#include <cuda_runtime.h>
#include <cuda_fp16.h>
#include <mma.h>
#include <math.h>

using namespace nvcuda;

#define NN   50000
#define EE   1600000
#define FIN  512
#define HH   8
#define HID  64
#define NCLS 7
#define NEG_SLOPE 0.2f
#define NB   196            // (NN+255)/256

// ---------------- scratch (device globals) -----------------------------------
__device__ int     g_cntR[NN], g_cntC[NN];
__device__ int     g_offR[NN + 1], g_offC[NN + 1];
__device__ int     g_curR[NN], g_curC[NN];
__device__ int     g_bsumR[256], g_bsumC[256], g_bprefR[256], g_bprefC[256];
__device__ int     g_sortedR[EE];   // edges sorted by col: stores row id
__device__ int     g_sortedC[EE];   // edges sorted by row: stores col id
__device__ __half2 g_xh_h [NN * 32];   // x @ W1, fp16 (32 half2 per node)
__device__ __half2 g_oute_h[NN * 32];  // hyperedge features, fp16
__device__ float   g_si  [NN * HH];
__device__ float   g_sj  [NN * HH];
__device__ float   g_rden[NN * HH];
__device__ float   g_Dinv[NN];
__device__ float   g_Binv[NN];
__device__ float   g_xh2 [NN * 8];     // h1 @ W2, padded 7->8
__device__ float   g_oute2[NN * 8];

__device__ __forceinline__ float lrelu(float a) { return a > 0.f ? a : NEG_SLOPE * a; }
// round-to-nearest tf32; result bits are a valid fp32 (truncated mantissa)
__device__ __forceinline__ float tf32r(float x) {
    unsigned r; asm("cvt.rna.tf32.f32 %0, %1;" : "=r"(r) : "f"(x));
    return __uint_as_float(r);
}

// ---------------- sort construction ------------------------------------------

__global__ void k_init() {
    int i = blockIdx.x * blockDim.x + threadIdx.x;
    if (i < NN) { g_cntR[i] = 0; g_cntC[i] = 0; }
    if (i == 0) { g_offR[NN] = EE; g_offC[NN] = EE; }
}

__global__ void k_count(const int* __restrict__ row, const int* __restrict__ col) {
    int e = (blockIdx.x * blockDim.x + threadIdx.x) * 2;
    if (e >= EE) return;
    int2 r = *(const int2*)&row[e];
    int2 c = *(const int2*)&col[e];
    atomicAdd(&g_cntR[r.x], 1);
    atomicAdd(&g_cntC[c.x], 1);
    atomicAdd(&g_cntR[r.y], 1);
    atomicAdd(&g_cntC[c.y], 1);
}

__global__ void k_bsum() {
    int t = threadIdx.x, b = blockIdx.x;
    int i = b * 256 + t;
    int vr = (i < NN) ? g_cntR[i] : 0;
    int vc = (i < NN) ? g_cntC[i] : 0;
    __shared__ int sr[8], sc[8];
#pragma unroll
    for (int o = 16; o; o >>= 1) {
        vr += __shfl_down_sync(~0u, vr, o);
        vc += __shfl_down_sync(~0u, vc, o);
    }
    if ((t & 31) == 0) { sr[t >> 5] = vr; sc[t >> 5] = vc; }
    __syncthreads();
    if (t < 8) {
        vr = sr[t]; vc = sc[t];
#pragma unroll
        for (int o = 4; o; o >>= 1) {
            vr += __shfl_down_sync(0xffu, vr, o);
            vc += __shfl_down_sync(0xffu, vc, o);
        }
        if (t == 0) { g_bsumR[b] = vr; g_bsumC[b] = vc; }
    }
}

__global__ void k_scanb() {
    __shared__ int s[256];
    int t = threadIdx.x;
    int v = (t < NB) ? g_bsumR[t] : 0;
    s[t] = v; __syncthreads();
    for (int d = 1; d < 256; d <<= 1) {
        int x = (t >= d) ? s[t - d] : 0; __syncthreads();
        s[t] += x; __syncthreads();
    }
    g_bprefR[t] = s[t] - v;
    __syncthreads();
    int vc = (t < NB) ? g_bsumC[t] : 0;
    s[t] = vc; __syncthreads();
    for (int d = 1; d < 256; d <<= 1) {
        int x = (t >= d) ? s[t - d] : 0; __syncthreads();
        s[t] += x; __syncthreads();
    }
    g_bprefC[t] = s[t] - vc;
}

__global__ void k_scanfin(const float* __restrict__ hw) {
    __shared__ int s[256];
    int t = threadIdx.x, b = blockIdx.x;
    int i = b * 256 + t;
    int v = (i < NN) ? g_cntR[i] : 0;
    s[t] = v; __syncthreads();
    for (int d = 1; d < 256; d <<= 1) {
        int x = (t >= d) ? s[t - d] : 0; __syncthreads();
        s[t] += x; __syncthreads();
    }
    if (i < NN) {
        int off = g_bprefR[b] + s[t] - v;
        g_offR[i] = off; g_curR[i] = off;
    }
    __syncthreads();
    int vc = (i < NN) ? g_cntC[i] : 0;
    s[t] = vc; __syncthreads();
    for (int d = 1; d < 256; d <<= 1) {
        int x = (t >= d) ? s[t - d] : 0; __syncthreads();
        s[t] += x; __syncthreads();
    }
    if (i < NN) {
        int off = g_bprefC[b] + s[t] - vc;
        g_offC[i] = off; g_curC[i] = off;
        g_Binv[i] = vc > 0 ? __ldg(&hw[i]) / (float)vc : 0.f;
    }
}

__global__ void k_scatter(const int* __restrict__ row, const int* __restrict__ col) {
    int e = (blockIdx.x * blockDim.x + threadIdx.x) * 2;
    if (e >= EE) return;
    int2 r = *(const int2*)&row[e];
    int2 c = *(const int2*)&col[e];
    int pc0 = atomicAdd(&g_curC[c.x], 1);
    int pr0 = atomicAdd(&g_curR[r.x], 1);
    int pc1 = atomicAdd(&g_curC[c.y], 1);
    int pr1 = atomicAdd(&g_curR[r.y], 1);
    g_sortedR[pc0] = r.x;
    g_sortedC[pr0] = c.x;
    g_sortedR[pc1] = r.y;
    g_sortedC[pr1] = c.y;
}

// ---------------- GEMM1 (tf32 3-term) + fused scores + fp16 store ------------
// xh = X[N,512] @ W1[512,64]; si/sj = head-wise dots with att
#define GM_BM 128
#define GM_BK 32
__global__ void k_gemm1(const float* __restrict__ X, const float* __restrict__ W,
                        const float* __restrict__ att) {
    __shared__ float smem[12288];            // 48KB
    float* sAhi = smem;                      // 128*32
    float* sAlo = smem + 4096;               // 128*32
    float* sBhi = smem + 8192;               // 32*64
    float* sBlo = smem + 10240;              // 32*64

    int tid = threadIdx.x;
    int warp = tid >> 5;
    int wm = warp >> 1;
    int wn = warp & 1;
    int bm = blockIdx.x * GM_BM;

    wmma::fragment<wmma::accumulator, 16, 16, 8, float> acc[2][2];
#pragma unroll
    for (int i = 0; i < 2; i++)
#pragma unroll
        for (int j = 0; j < 2; j++) wmma::fill_fragment(acc[i][j], 0.f);

    for (int k0 = 0; k0 < FIN; k0 += GM_BK) {
#pragma unroll
        for (int l = 0; l < 4; l++) {        // A tile
            int p = tid + l * 256;
            int m = p >> 3;
            int k4 = (p & 7) << 2;
            float4 v = make_float4(0.f, 0.f, 0.f, 0.f);
            if (bm + m < NN) v = *(const float4*)&X[(size_t)(bm + m) * FIN + k0 + k4];
            float h0 = tf32r(v.x), h1 = tf32r(v.y), h2 = tf32r(v.z), h3 = tf32r(v.w);
            float* hi = &sAhi[m * GM_BK + k4];
            float* lo = &sAlo[m * GM_BK + k4];
            hi[0] = h0; hi[1] = h1; hi[2] = h2; hi[3] = h3;
            lo[0] = tf32r(v.x - h0); lo[1] = tf32r(v.y - h1);
            lo[2] = tf32r(v.z - h2); lo[3] = tf32r(v.w - h3);
        }
#pragma unroll
        for (int l = 0; l < 2; l++) {        // B tile
            int p = tid + l * 256;
            int k = p >> 4;
            int n4 = (p & 15) << 2;
            float4 v = *(const float4*)&W[(size_t)(k0 + k) * 64 + n4];
            float h0 = tf32r(v.x), h1 = tf32r(v.y), h2 = tf32r(v.z), h3 = tf32r(v.w);
            float* hi = &sBhi[k * 64 + n4];
            float* lo = &sBlo[k * 64 + n4];
            hi[0] = h0; hi[1] = h1; hi[2] = h2; hi[3] = h3;
            lo[0] = tf32r(v.x - h0); lo[1] = tf32r(v.y - h1);
            lo[2] = tf32r(v.z - h2); lo[3] = tf32r(v.w - h3);
        }
        __syncthreads();
#pragma unroll
        for (int kk = 0; kk < GM_BK; kk += 8) {
            wmma::fragment<wmma::matrix_a, 16, 16, 8, wmma::precision::tf32, wmma::row_major> aHi[2], aLo[2];
            wmma::fragment<wmma::matrix_b, 16, 16, 8, wmma::precision::tf32, wmma::row_major> bHi[2], bLo[2];
#pragma unroll
            for (int i = 0; i < 2; i++) {
                wmma::load_matrix_sync(aHi[i], &sAhi[(wm * 32 + i * 16) * GM_BK + kk], GM_BK);
                wmma::load_matrix_sync(aLo[i], &sAlo[(wm * 32 + i * 16) * GM_BK + kk], GM_BK);
            }
#pragma unroll
            for (int j = 0; j < 2; j++) {
                wmma::load_matrix_sync(bHi[j], &sBhi[kk * 64 + wn * 32 + j * 16], 64);
                wmma::load_matrix_sync(bLo[j], &sBlo[kk * 64 + wn * 32 + j * 16], 64);
            }
#pragma unroll
            for (int i = 0; i < 2; i++)
#pragma unroll
                for (int j = 0; j < 2; j++) {
                    wmma::mma_sync(acc[i][j], aHi[i], bHi[j], acc[i][j]);
                    wmma::mma_sync(acc[i][j], aHi[i], bLo[j], acc[i][j]);
                    wmma::mma_sync(acc[i][j], aLo[i], bHi[j], acc[i][j]);
                }
        }
        __syncthreads();
    }
    float* sC = smem;                        // 128*64
#pragma unroll
    for (int i = 0; i < 2; i++)
#pragma unroll
        for (int j = 0; j < 2; j++)
            wmma::store_matrix_sync(&sC[(wm * 32 + i * 16) * 64 + wn * 32 + j * 16],
                                    acc[i][j], 64, wmma::mem_row_major);
    __syncthreads();
    // fused scores (fp32 accuracy) -- 1024 (m,h) pairs, 4 per thread
#pragma unroll
    for (int l = 0; l < 4; l++) {
        int p = tid + l * 256;
        int m = p >> 3, h = p & 7;
        if (bm + m < NN) {
            const float* xr = &sC[m * 64 + h * 8];
            float si = 0.f, sj = 0.f;
#pragma unroll
            for (int c = 0; c < 8; c++) {
                float v = xr[c];
                si += v * __ldg(&att[h * 16 + c]);
                sj += v * __ldg(&att[h * 16 + 8 + c]);
            }
            g_si[(bm + m) * 8 + h] = si;
            g_sj[(bm + m) * 8 + h] = sj;
        }
    }
    // fp16 feature store: 4096 half2, 16 per thread
#pragma unroll
    for (int l = 0; l < 16; l++) {
        int p = tid + l * 256;
        int m = p >> 5, f2 = p & 31;
        if (bm + m < NN)
            g_xh_h[(size_t)(bm + m) * 32 + f2] =
                __floats2half2_rn(sC[m * 64 + f2 * 2], sC[m * 64 + f2 * 2 + 1]);
    }
}

// ---------------- denominator + Dinv (warp per node, by-row CSR) --------------
__global__ void k_den(const float* __restrict__ hw) {
    int w = (blockIdx.x * blockDim.x + threadIdx.x) >> 5;
    if (w >= NN) return;
    int lane = threadIdx.x & 31;
    int g = lane >> 3, h = lane & 7;
    int start = g_offR[w], end = g_offR[w + 1];
    float si_h = g_si[w * 8 + h];
    float den = 0.f, Dacc = 0.f;
    int i = start + g;
    for (; i + 4 < end; i += 8) {
        int c0 = g_sortedC[i];
        int c1 = g_sortedC[i + 4];
        float sj0 = __ldg(&g_sj[c0 * 8 + h]);
        float sj1 = __ldg(&g_sj[c1 * 8 + h]);
        den += __expf(lrelu(si_h + sj0)) + __expf(lrelu(si_h + sj1));
        if (h == 0) Dacc += __ldg(&hw[c0]) + __ldg(&hw[c1]);
    }
    if (i < end) {
        int c0 = g_sortedC[i];
        den += __expf(lrelu(si_h + __ldg(&g_sj[c0 * 8 + h])));
        if (h == 0) Dacc += __ldg(&hw[c0]);
    }
    den += __shfl_xor_sync(~0u, den, 8);
    den += __shfl_xor_sync(~0u, den, 16);
    Dacc += __shfl_xor_sync(~0u, Dacc, 8);
    Dacc += __shfl_xor_sync(~0u, Dacc, 16);
    if (g == 0) g_rden[w * 8 + h] = 1.0f / (den + 1e-16f);
    if (lane == 0) g_Dinv[w] = Dacc > 0.f ? 1.0f / Dacc : 0.f;
}

// ---------------- prop1: nodes -> hyperedges (warp per hyperedge, fp16) -------
__global__ void k_prop1() {
    int w = (blockIdx.x * blockDim.x + threadIdx.x) >> 5;
    if (w >= NN) return;
    int lane = threadIdx.x & 31;
    int h = lane >> 2;
    int start = g_offC[w], end = g_offC[w + 1];
    float sj_h = g_sj[w * 8 + h];
    float binv = g_Binv[w];
    float ax = 0.f, ay = 0.f;
    int i = start;
    for (; i + 3 < end; i += 4) {
        int r0 = g_sortedR[i], r1 = g_sortedR[i + 1];
        int r2 = g_sortedR[i + 2], r3 = g_sortedR[i + 3];
        float si0 = __ldg(&g_si[r0 * 8 + h]), si1 = __ldg(&g_si[r1 * 8 + h]);
        float si2 = __ldg(&g_si[r2 * 8 + h]), si3 = __ldg(&g_si[r3 * 8 + h]);
        float rd0 = __ldg(&g_rden[r0 * 8 + h]), rd1 = __ldg(&g_rden[r1 * 8 + h]);
        float rd2 = __ldg(&g_rden[r2 * 8 + h]), rd3 = __ldg(&g_rden[r3 * 8 + h]);
        float2 f0 = __half22float2(g_xh_h[(size_t)r0 * 32 + lane]);
        float2 f1 = __half22float2(g_xh_h[(size_t)r1 * 32 + lane]);
        float2 f2 = __half22float2(g_xh_h[(size_t)r2 * 32 + lane]);
        float2 f3 = __half22float2(g_xh_h[(size_t)r3 * 32 + lane]);
        float w0 = __expf(lrelu(si0 + sj_h)) * rd0;
        float w1 = __expf(lrelu(si1 + sj_h)) * rd1;
        float w2 = __expf(lrelu(si2 + sj_h)) * rd2;
        float w3 = __expf(lrelu(si3 + sj_h)) * rd3;
        ax += w0 * f0.x + w1 * f1.x + w2 * f2.x + w3 * f3.x;
        ay += w0 * f0.y + w1 * f1.y + w2 * f2.y + w3 * f3.y;
    }
    for (; i < end; i++) {
        int r0 = g_sortedR[i];
        float si0 = __ldg(&g_si[r0 * 8 + h]);
        float rd0 = __ldg(&g_rden[r0 * 8 + h]);
        float2 f0 = __half22float2(g_xh_h[(size_t)r0 * 32 + lane]);
        float w0 = __expf(lrelu(si0 + sj_h)) * rd0;
        ax += w0 * f0.x; ay += w0 * f0.y;
    }
    g_oute_h[(size_t)w * 32 + lane] = __floats2half2_rn(ax * binv, ay * binv);
}

// ------- prop2 (fp16 gather) + bias + ELU + fused gemm2 (h1 never stored) -----
__global__ void k_prop2(const float* __restrict__ b1, const float* __restrict__ W2) {
    __shared__ float sW[448];
    for (int i = threadIdx.x; i < 448; i += 256) sW[i] = W2[i];
    __syncthreads();
    int w = (blockIdx.x * blockDim.x + threadIdx.x) >> 5;
    if (w >= NN) return;
    int lane = threadIdx.x & 31;
    int h = lane >> 2;
    int start = g_offR[w], end = g_offR[w + 1];
    float si_h = g_si[w * 8 + h];
    float rd_h = g_rden[w * 8 + h];
    float dinv = g_Dinv[w];
    float ax = 0.f, ay = 0.f;
    int i = start;
    for (; i + 3 < end; i += 4) {
        int c0 = g_sortedC[i], c1 = g_sortedC[i + 1];
        int c2 = g_sortedC[i + 2], c3 = g_sortedC[i + 3];
        float sj0 = __ldg(&g_sj[c0 * 8 + h]), sj1 = __ldg(&g_sj[c1 * 8 + h]);
        float sj2 = __ldg(&g_sj[c2 * 8 + h]), sj3 = __ldg(&g_sj[c3 * 8 + h]);
        float2 f0 = __half22float2(g_oute_h[(size_t)c0 * 32 + lane]);
        float2 f1 = __half22float2(g_oute_h[(size_t)c1 * 32 + lane]);
        float2 f2 = __half22float2(g_oute_h[(size_t)c2 * 32 + lane]);
        float2 f3 = __half22float2(g_oute_h[(size_t)c3 * 32 + lane]);
        float w0 = __expf(lrelu(si_h + sj0)) * rd_h;
        float w1 = __expf(lrelu(si_h + sj1)) * rd_h;
        float w2 = __expf(lrelu(si_h + sj2)) * rd_h;
        float w3 = __expf(lrelu(si_h + sj3)) * rd_h;
        ax += w0 * f0.x + w1 * f1.x + w2 * f2.x + w3 * f3.x;
        ay += w0 * f0.y + w1 * f1.y + w2 * f2.y + w3 * f3.y;
    }
    for (; i < end; i++) {
        int c0 = g_sortedC[i];
        float sj0 = __ldg(&g_sj[c0 * 8 + h]);
        float2 f0 = __half22float2(g_oute_h[(size_t)c0 * 32 + lane]);
        float w0 = __expf(lrelu(si_h + sj0)) * rd_h;
        ax += w0 * f0.x; ay += w0 * f0.y;
    }
    // bias + ELU -> h1 row lives in registers (2 floats per lane)
    float vx = ax * dinv + __ldg(&b1[lane * 2]);
    float vy = ay * dinv + __ldg(&b1[lane * 2 + 1]);
    vx = vx > 0.f ? vx : expm1f(vx);
    vy = vy > 0.f ? vy : expm1f(vy);
    // fused gemm2: xh2[w, j] = sum_k h1[k] * W2[k, j]
    float a7[7];
#pragma unroll
    for (int j = 0; j < 7; j++)
        a7[j] = vx * sW[(lane * 2) * 7 + j] + vy * sW[(lane * 2 + 1) * 7 + j];
#pragma unroll
    for (int off = 16; off; off >>= 1)
#pragma unroll
        for (int j = 0; j < 7; j++)
            a7[j] += __shfl_xor_sync(~0u, a7[j], off);
    if (lane == 0) {
        float4* o = (float4*)&g_xh2[w * 8];
        o[0] = make_float4(a7[0], a7[1], a7[2], a7[3]);
        o[1] = make_float4(a7[4], a7[5], a7[6], 0.f);
    }
}

// ---------------- layer-2 propagation (warp per segment) ----------------------
__global__ void k2_prop1() {
    int w = (blockIdx.x * blockDim.x + threadIdx.x) >> 5;
    if (w >= NN) return;
    int lane = threadIdx.x & 31;
    int g = lane >> 3, j = lane & 7;
    int start = g_offC[w], end = g_offC[w + 1];
    float acc = 0.f;
    int i = start + g;
    for (; i + 4 < end; i += 8) {
        int r0 = g_sortedR[i], r1 = g_sortedR[i + 4];
        acc += __ldg(&g_xh2[r0 * 8 + j]) + __ldg(&g_xh2[r1 * 8 + j]);
    }
    if (i < end) acc += __ldg(&g_xh2[g_sortedR[i] * 8 + j]);
    acc += __shfl_xor_sync(~0u, acc, 8);
    acc += __shfl_xor_sync(~0u, acc, 16);
    if (g == 0) g_oute2[w * 8 + j] = acc * g_Binv[w];
}

// k2_prop2 + fused log_softmax
__global__ void k2_prop2(const float* __restrict__ b2, float* __restrict__ out) {
    int w = (blockIdx.x * blockDim.x + threadIdx.x) >> 5;
    if (w >= NN) return;
    int lane = threadIdx.x & 31;
    int g = lane >> 3, j = lane & 7;
    int start = g_offR[w], end = g_offR[w + 1];
    float acc = 0.f;
    int i = start + g;
    for (; i + 4 < end; i += 8) {
        int c0 = g_sortedC[i], c1 = g_sortedC[i + 4];
        acc += __ldg(&g_oute2[c0 * 8 + j]) + __ldg(&g_oute2[c1 * 8 + j]);
    }
    if (i < end) acc += __ldg(&g_oute2[g_sortedC[i] * 8 + j]);
    acc += __shfl_xor_sync(~0u, acc, 8);
    acc += __shfl_xor_sync(~0u, acc, 16);
    // all lanes now hold total for class j = lane&7 (replicated over 4 groups)
    float v = (j < 7) ? acc * g_Dinv[w] + __ldg(&b2[j]) : -1e30f;
    float m = v;
#pragma unroll
    for (int off = 1; off < 8; off <<= 1)
        m = fmaxf(m, __shfl_xor_sync(~0u, m, off));
    float ex = (j < 7) ? __expf(v - m) : 0.f;
    float s = ex;
#pragma unroll
    for (int off = 1; off < 8; off <<= 1)
        s += __shfl_xor_sync(~0u, s, off);
    if (g == 0 && j < 7)
        out[(size_t)w * NCLS + j] = v - m - logf(s);
}

// ---------------- launch ------------------------------------------------------

extern "C" void kernel_launch(void* const* d_in, const int* in_sizes, int n_in,
                              void* d_out, int out_size) {
    const float* x   = (const float*)d_in[0];
    const int*   ei  = (const int*)  d_in[1];
    const float* hw  = (const float*)d_in[2];
    const float* W1  = (const float*)d_in[3];
    const float* att = (const float*)d_in[4];
    const float* b1  = (const float*)d_in[5];
    const float* W2  = (const float*)d_in[6];
    const float* b2  = (const float*)d_in[7];
    float* out = (float*)d_out;

    const int* row = ei;        // edge_index[0]
    const int* col = ei + EE;   // edge_index[1]

    const int EB2 = (EE / 2 + 255) / 256;     // 3125 (2 edges/thread)
    const int WB  = (NN * 32 + 255) / 256;    // 6250 (warp-per-segment kernels)

    k_init<<<NB, 256>>>();
    k_count<<<EB2, 256>>>(row, col);
    k_bsum<<<NB, 256>>>();
    k_scanb<<<1, 256>>>();
    k_scanfin<<<NB, 256>>>(hw);
    k_scatter<<<EB2, 256>>>(row, col);
    k_gemm1<<<(NN + GM_BM - 1) / GM_BM, 256>>>(x, W1, att);
    k_den<<<WB, 256>>>(hw);
    k_prop1<<<WB, 256>>>();
    k_prop2<<<WB, 256>>>(b1, W2);
    k2_prop1<<<WB, 256>>>();
    k2_prop2<<<WB, 256>>>(b2, out);
}

// round 6
// speedup vs baseline: 3.6660x; 1.3049x over previous
#include <cuda_runtime.h>
#include <cuda_fp16.h>
#include <mma.h>
#include <math.h>

using namespace nvcuda;

#define NN   50000
#define EE   1600000
#define FIN  512
#define HH   8
#define HID  64
#define NCLS 7
#define NEG_SLOPE 0.2f
#define NB   196            // (NN+255)/256

// ---------------- scratch (device globals) -----------------------------------
__device__ int     g_cntR[NN], g_cntC[NN];
__device__ int     g_offR[NN + 1], g_offC[NN + 1];
__device__ int     g_curR[NN], g_curC[NN];
__device__ int     g_bsumR[256], g_bsumC[256], g_bprefR[256], g_bprefC[256];
__device__ int     g_ctr;
__device__ int     g_sortedR[EE];   // edges sorted by col: stores row id
__device__ int     g_sortedC[EE];   // edges sorted by row: stores col id
__device__ __half2 g_xh_h [NN * 32];   // x @ W1, fp16 (32 half2 per node)
__device__ __half2 g_oute_h[NN * 32];  // hyperedge features, fp16
__device__ float   g_sird[NN * 16];    // interleaved (si, rden) per (node, head)
__device__ float   g_sj  [NN * HH];
__device__ float   g_Dinv[NN];
__device__ float   g_Binv[NN];
__device__ float   g_xh2 [NN * 8];     // h1 @ W2, padded 7->8
__device__ float   g_oute2[NN * 8];

__device__ __forceinline__ float lrelu(float a) { return a > 0.f ? a : NEG_SLOPE * a; }
__device__ __forceinline__ float tf32r(float x) {
    unsigned r; asm("cvt.rna.tf32.f32 %0, %1;" : "=r"(r) : "f"(x));
    return __uint_as_float(r);
}

// ---------------- sort construction ------------------------------------------

__global__ void k_init() {
    int i = blockIdx.x * blockDim.x + threadIdx.x;
    if (i < NN) { g_cntR[i] = 0; g_cntC[i] = 0; }
    if (i == 0) { g_offR[NN] = EE; g_offC[NN] = EE; g_ctr = 0; }
}

__global__ void k_count(const int* __restrict__ row, const int* __restrict__ col) {
    int e = (blockIdx.x * blockDim.x + threadIdx.x) * 2;
    if (e >= EE) return;
    int2 r = *(const int2*)&row[e];
    int2 c = *(const int2*)&col[e];
    atomicAdd(&g_cntR[r.x], 1);
    atomicAdd(&g_cntC[c.x], 1);
    atomicAdd(&g_cntR[r.y], 1);
    atomicAdd(&g_cntC[c.y], 1);
}

// fused: per-block partial sums + (last block) scan of the 196 partials
__global__ void k_bsum_scan() {
    int t = threadIdx.x, b = blockIdx.x;
    int i = b * 256 + t;
    int vr = (i < NN) ? g_cntR[i] : 0;
    int vc = (i < NN) ? g_cntC[i] : 0;
    __shared__ int sr[8], sc[8];
    __shared__ int s_last;
#pragma unroll
    for (int o = 16; o; o >>= 1) {
        vr += __shfl_down_sync(~0u, vr, o);
        vc += __shfl_down_sync(~0u, vc, o);
    }
    if ((t & 31) == 0) { sr[t >> 5] = vr; sc[t >> 5] = vc; }
    __syncthreads();
    if (t < 8) {
        vr = sr[t]; vc = sc[t];
#pragma unroll
        for (int o = 4; o; o >>= 1) {
            vr += __shfl_down_sync(0xffu, vr, o);
            vc += __shfl_down_sync(0xffu, vc, o);
        }
        if (t == 0) { g_bsumR[b] = vr; g_bsumC[b] = vc; }
    }
    __threadfence();
    if (t == 0) s_last = (atomicAdd(&g_ctr, 1) == gridDim.x - 1);
    __syncthreads();
    if (!s_last) return;
    // last block scans the partials
    __shared__ int s[256];
    int v = (t < NB) ? g_bsumR[t] : 0;
    s[t] = v; __syncthreads();
    for (int d = 1; d < 256; d <<= 1) {
        int x = (t >= d) ? s[t - d] : 0; __syncthreads();
        s[t] += x; __syncthreads();
    }
    g_bprefR[t] = s[t] - v;
    __syncthreads();
    int vc2 = (t < NB) ? g_bsumC[t] : 0;
    s[t] = vc2; __syncthreads();
    for (int d = 1; d < 256; d <<= 1) {
        int x = (t >= d) ? s[t - d] : 0; __syncthreads();
        s[t] += x; __syncthreads();
    }
    g_bprefC[t] = s[t] - vc2;
}

__global__ void k_scanfin(const float* __restrict__ hw) {
    __shared__ int s[256];
    int t = threadIdx.x, b = blockIdx.x;
    int i = b * 256 + t;
    int v = (i < NN) ? g_cntR[i] : 0;
    s[t] = v; __syncthreads();
    for (int d = 1; d < 256; d <<= 1) {
        int x = (t >= d) ? s[t - d] : 0; __syncthreads();
        s[t] += x; __syncthreads();
    }
    if (i < NN) {
        int off = g_bprefR[b] + s[t] - v;
        g_offR[i] = off; g_curR[i] = off;
    }
    __syncthreads();
    int vc = (i < NN) ? g_cntC[i] : 0;
    s[t] = vc; __syncthreads();
    for (int d = 1; d < 256; d <<= 1) {
        int x = (t >= d) ? s[t - d] : 0; __syncthreads();
        s[t] += x; __syncthreads();
    }
    if (i < NN) {
        int off = g_bprefC[b] + s[t] - vc;
        g_offC[i] = off; g_curC[i] = off;
        g_Binv[i] = vc > 0 ? __ldg(&hw[i]) / (float)vc : 0.f;
    }
}

__global__ void k_scatter(const int* __restrict__ row, const int* __restrict__ col) {
    int e = (blockIdx.x * blockDim.x + threadIdx.x) * 2;
    if (e >= EE) return;
    int2 r = *(const int2*)&row[e];
    int2 c = *(const int2*)&col[e];
    int pc0 = atomicAdd(&g_curC[c.x], 1);
    int pr0 = atomicAdd(&g_curR[r.x], 1);
    int pc1 = atomicAdd(&g_curC[c.y], 1);
    int pr1 = atomicAdd(&g_curR[r.y], 1);
    g_sortedR[pc0] = r.x;
    g_sortedC[pr0] = c.x;
    g_sortedR[pc1] = r.y;
    g_sortedC[pr1] = c.y;
}

// ---------------- GEMM1 (tf32 single-term) + fused scores + fp16 store -------
#define GM_BM 128
#define GM_BK 32
__global__ void k_gemm1(const float* __restrict__ X, const float* __restrict__ W,
                        const float* __restrict__ att) {
    __shared__ float smem[8192];             // 32KB (epilogue C reuses all of it)
    float* sA = smem;                        // 128*32
    float* sB = smem + 4096;                 // 32*64

    int tid = threadIdx.x;
    int warp = tid >> 5;
    int wm = warp >> 1;
    int wn = warp & 1;
    int bm = blockIdx.x * GM_BM;

    wmma::fragment<wmma::accumulator, 16, 16, 8, float> acc[2][2];
#pragma unroll
    for (int i = 0; i < 2; i++)
#pragma unroll
        for (int j = 0; j < 2; j++) wmma::fill_fragment(acc[i][j], 0.f);

    for (int k0 = 0; k0 < FIN; k0 += GM_BK) {
#pragma unroll
        for (int l = 0; l < 4; l++) {        // A tile: 128x32 = 1024 float4
            int p = tid + l * 256;
            int m = p >> 3;
            int k4 = (p & 7) << 2;
            float4 v = make_float4(0.f, 0.f, 0.f, 0.f);
            if (bm + m < NN) v = *(const float4*)&X[(size_t)(bm + m) * FIN + k0 + k4];
            float* d = &sA[m * GM_BK + k4];
            d[0] = tf32r(v.x); d[1] = tf32r(v.y); d[2] = tf32r(v.z); d[3] = tf32r(v.w);
        }
#pragma unroll
        for (int l = 0; l < 2; l++) {        // B tile: 32x64 = 512 float4
            int p = tid + l * 256;
            int k = p >> 4;
            int n4 = (p & 15) << 2;
            float4 v = *(const float4*)&W[(size_t)(k0 + k) * 64 + n4];
            float* d = &sB[k * 64 + n4];
            d[0] = tf32r(v.x); d[1] = tf32r(v.y); d[2] = tf32r(v.z); d[3] = tf32r(v.w);
        }
        __syncthreads();
#pragma unroll
        for (int kk = 0; kk < GM_BK; kk += 8) {
            wmma::fragment<wmma::matrix_a, 16, 16, 8, wmma::precision::tf32, wmma::row_major> a[2];
            wmma::fragment<wmma::matrix_b, 16, 16, 8, wmma::precision::tf32, wmma::row_major> b[2];
#pragma unroll
            for (int i = 0; i < 2; i++)
                wmma::load_matrix_sync(a[i], &sA[(wm * 32 + i * 16) * GM_BK + kk], GM_BK);
#pragma unroll
            for (int j = 0; j < 2; j++)
                wmma::load_matrix_sync(b[j], &sB[kk * 64 + wn * 32 + j * 16], 64);
#pragma unroll
            for (int i = 0; i < 2; i++)
#pragma unroll
                for (int j = 0; j < 2; j++)
                    wmma::mma_sync(acc[i][j], a[i], b[j], acc[i][j]);
        }
        __syncthreads();
    }
    float* sC = smem;                        // 128*64
#pragma unroll
    for (int i = 0; i < 2; i++)
#pragma unroll
        for (int j = 0; j < 2; j++)
            wmma::store_matrix_sync(&sC[(wm * 32 + i * 16) * 64 + wn * 32 + j * 16],
                                    acc[i][j], 64, wmma::mem_row_major);
    __syncthreads();
    // fused scores: si -> g_sird[.x], sj -> g_sj
#pragma unroll
    for (int l = 0; l < 4; l++) {
        int p = tid + l * 256;
        int m = p >> 3, h = p & 7;
        if (bm + m < NN) {
            const float* xr = &sC[m * 64 + h * 8];
            float si = 0.f, sj = 0.f;
#pragma unroll
            for (int c = 0; c < 8; c++) {
                float v = xr[c];
                si += v * __ldg(&att[h * 16 + c]);
                sj += v * __ldg(&att[h * 16 + 8 + c]);
            }
            g_sird[((bm + m) * 8 + h) * 2] = si;
            g_sj[(bm + m) * 8 + h] = sj;
        }
    }
    // fp16 feature store: 4096 half2, 16 per thread
#pragma unroll
    for (int l = 0; l < 16; l++) {
        int p = tid + l * 256;
        int m = p >> 5, f2 = p & 31;
        if (bm + m < NN)
            g_xh_h[(size_t)(bm + m) * 32 + f2] =
                __floats2half2_rn(sC[m * 64 + f2 * 2], sC[m * 64 + f2 * 2 + 1]);
    }
}

// ---------------- denominator + Dinv (warp per node, by-row CSR) --------------
__global__ void k_den(const float* __restrict__ hw) {
    int w = (blockIdx.x * blockDim.x + threadIdx.x) >> 5;
    if (w >= NN) return;
    int lane = threadIdx.x & 31;
    int g = lane >> 3, h = lane & 7;
    int start = g_offR[w], end = g_offR[w + 1];
    float si_h = g_sird[(w * 8 + h) * 2];
    float den = 0.f, Dacc = 0.f;
    int i = start + g;
    for (; i + 4 < end; i += 8) {
        int c0 = g_sortedC[i];
        int c1 = g_sortedC[i + 4];
        float sj0 = __ldg(&g_sj[c0 * 8 + h]);
        float sj1 = __ldg(&g_sj[c1 * 8 + h]);
        den += __expf(lrelu(si_h + sj0)) + __expf(lrelu(si_h + sj1));
        if (h == 0) Dacc += __ldg(&hw[c0]) + __ldg(&hw[c1]);
    }
    if (i < end) {
        int c0 = g_sortedC[i];
        den += __expf(lrelu(si_h + __ldg(&g_sj[c0 * 8 + h])));
        if (h == 0) Dacc += __ldg(&hw[c0]);
    }
    den += __shfl_xor_sync(~0u, den, 8);
    den += __shfl_xor_sync(~0u, den, 16);
    Dacc += __shfl_xor_sync(~0u, Dacc, 8);
    Dacc += __shfl_xor_sync(~0u, Dacc, 16);
    if (g == 0) g_sird[(w * 8 + h) * 2 + 1] = 1.0f / (den + 1e-16f);
    if (lane == 0) g_Dinv[w] = Dacc > 0.f ? 1.0f / Dacc : 0.f;
}

// ---------------- prop1: nodes -> hyperedges (warp per hyperedge, fp16) -------
__global__ void k_prop1() {
    int w = (blockIdx.x * blockDim.x + threadIdx.x) >> 5;
    if (w >= NN) return;
    int lane = threadIdx.x & 31;
    int h = lane >> 2;
    int start = g_offC[w], end = g_offC[w + 1];
    float sj_h = g_sj[w * 8 + h];
    float binv = g_Binv[w];
    float ax = 0.f, ay = 0.f;
    int i = start;
    for (; i + 3 < end; i += 4) {
        int r0 = g_sortedR[i], r1 = g_sortedR[i + 1];
        int r2 = g_sortedR[i + 2], r3 = g_sortedR[i + 3];
        float2 sr0 = *(const float2*)&g_sird[(r0 * 8 + h) * 2];
        float2 sr1 = *(const float2*)&g_sird[(r1 * 8 + h) * 2];
        float2 sr2 = *(const float2*)&g_sird[(r2 * 8 + h) * 2];
        float2 sr3 = *(const float2*)&g_sird[(r3 * 8 + h) * 2];
        float2 f0 = __half22float2(g_xh_h[(size_t)r0 * 32 + lane]);
        float2 f1 = __half22float2(g_xh_h[(size_t)r1 * 32 + lane]);
        float2 f2 = __half22float2(g_xh_h[(size_t)r2 * 32 + lane]);
        float2 f3 = __half22float2(g_xh_h[(size_t)r3 * 32 + lane]);
        float w0 = __expf(lrelu(sr0.x + sj_h)) * sr0.y;
        float w1 = __expf(lrelu(sr1.x + sj_h)) * sr1.y;
        float w2 = __expf(lrelu(sr2.x + sj_h)) * sr2.y;
        float w3 = __expf(lrelu(sr3.x + sj_h)) * sr3.y;
        ax += w0 * f0.x + w1 * f1.x + w2 * f2.x + w3 * f3.x;
        ay += w0 * f0.y + w1 * f1.y + w2 * f2.y + w3 * f3.y;
    }
    for (; i < end; i++) {
        int r0 = g_sortedR[i];
        float2 sr0 = *(const float2*)&g_sird[(r0 * 8 + h) * 2];
        float2 f0 = __half22float2(g_xh_h[(size_t)r0 * 32 + lane]);
        float w0 = __expf(lrelu(sr0.x + sj_h)) * sr0.y;
        ax += w0 * f0.x; ay += w0 * f0.y;
    }
    g_oute_h[(size_t)w * 32 + lane] = __floats2half2_rn(ax * binv, ay * binv);
}

// ------- prop2 (fp16 gather) + bias + ELU + fused gemm2 (h1 never stored) -----
__global__ void k_prop2(const float* __restrict__ b1, const float* __restrict__ W2) {
    __shared__ float sW[448];
    for (int i = threadIdx.x; i < 448; i += 256) sW[i] = W2[i];
    __syncthreads();
    int w = (blockIdx.x * blockDim.x + threadIdx.x) >> 5;
    if (w >= NN) return;
    int lane = threadIdx.x & 31;
    int h = lane >> 2;
    int start = g_offR[w], end = g_offR[w + 1];
    float2 sr = *(const float2*)&g_sird[(w * 8 + h) * 2];
    float si_h = sr.x, rd_h = sr.y;
    float dinv = g_Dinv[w];
    float ax = 0.f, ay = 0.f;
    int i = start;
    for (; i + 3 < end; i += 4) {
        int c0 = g_sortedC[i], c1 = g_sortedC[i + 1];
        int c2 = g_sortedC[i + 2], c3 = g_sortedC[i + 3];
        float sj0 = __ldg(&g_sj[c0 * 8 + h]), sj1 = __ldg(&g_sj[c1 * 8 + h]);
        float sj2 = __ldg(&g_sj[c2 * 8 + h]), sj3 = __ldg(&g_sj[c3 * 8 + h]);
        float2 f0 = __half22float2(g_oute_h[(size_t)c0 * 32 + lane]);
        float2 f1 = __half22float2(g_oute_h[(size_t)c1 * 32 + lane]);
        float2 f2 = __half22float2(g_oute_h[(size_t)c2 * 32 + lane]);
        float2 f3 = __half22float2(g_oute_h[(size_t)c3 * 32 + lane]);
        float w0 = __expf(lrelu(si_h + sj0)) * rd_h;
        float w1 = __expf(lrelu(si_h + sj1)) * rd_h;
        float w2 = __expf(lrelu(si_h + sj2)) * rd_h;
        float w3 = __expf(lrelu(si_h + sj3)) * rd_h;
        ax += w0 * f0.x + w1 * f1.x + w2 * f2.x + w3 * f3.x;
        ay += w0 * f0.y + w1 * f1.y + w2 * f2.y + w3 * f3.y;
    }
    for (; i < end; i++) {
        int c0 = g_sortedC[i];
        float sj0 = __ldg(&g_sj[c0 * 8 + h]);
        float2 f0 = __half22float2(g_oute_h[(size_t)c0 * 32 + lane]);
        float w0 = __expf(lrelu(si_h + sj0)) * rd_h;
        ax += w0 * f0.x; ay += w0 * f0.y;
    }
    float vx = ax * dinv + __ldg(&b1[lane * 2]);
    float vy = ay * dinv + __ldg(&b1[lane * 2 + 1]);
    vx = vx > 0.f ? vx : expm1f(vx);
    vy = vy > 0.f ? vy : expm1f(vy);
    float a7[7];
#pragma unroll
    for (int j = 0; j < 7; j++)
        a7[j] = vx * sW[(lane * 2) * 7 + j] + vy * sW[(lane * 2 + 1) * 7 + j];
#pragma unroll
    for (int off = 16; off; off >>= 1)
#pragma unroll
        for (int j = 0; j < 7; j++)
            a7[j] += __shfl_xor_sync(~0u, a7[j], off);
    if (lane == 0) {
        float4* o = (float4*)&g_xh2[w * 8];
        o[0] = make_float4(a7[0], a7[1], a7[2], a7[3]);
        o[1] = make_float4(a7[4], a7[5], a7[6], 0.f);
    }
}

// ---------------- layer-2 propagation (warp per segment) ----------------------
__global__ void k2_prop1() {
    int w = (blockIdx.x * blockDim.x + threadIdx.x) >> 5;
    if (w >= NN) return;
    int lane = threadIdx.x & 31;
    int g = lane >> 3, j = lane & 7;
    int start = g_offC[w], end = g_offC[w + 1];
    float acc = 0.f;
    int i = start + g;
    for (; i + 4 < end; i += 8) {
        int r0 = g_sortedR[i], r1 = g_sortedR[i + 4];
        acc += __ldg(&g_xh2[r0 * 8 + j]) + __ldg(&g_xh2[r1 * 8 + j]);
    }
    if (i < end) acc += __ldg(&g_xh2[g_sortedR[i] * 8 + j]);
    acc += __shfl_xor_sync(~0u, acc, 8);
    acc += __shfl_xor_sync(~0u, acc, 16);
    if (g == 0) g_oute2[w * 8 + j] = acc * g_Binv[w];
}

// k2_prop2 + fused log_softmax
__global__ void k2_prop2(const float* __restrict__ b2, float* __restrict__ out) {
    int w = (blockIdx.x * blockDim.x + threadIdx.x) >> 5;
    if (w >= NN) return;
    int lane = threadIdx.x & 31;
    int g = lane >> 3, j = lane & 7;
    int start = g_offR[w], end = g_offR[w + 1];
    float acc = 0.f;
    int i = start + g;
    for (; i + 4 < end; i += 8) {
        int c0 = g_sortedC[i], c1 = g_sortedC[i + 4];
        acc += __ldg(&g_oute2[c0 * 8 + j]) + __ldg(&g_oute2[c1 * 8 + j]);
    }
    if (i < end) acc += __ldg(&g_oute2[g_sortedC[i] * 8 + j]);
    acc += __shfl_xor_sync(~0u, acc, 8);
    acc += __shfl_xor_sync(~0u, acc, 16);
    float v = (j < 7) ? acc * g_Dinv[w] + __ldg(&b2[j]) : -1e30f;
    float m = v;
#pragma unroll
    for (int off = 1; off < 8; off <<= 1)
        m = fmaxf(m, __shfl_xor_sync(~0u, m, off));
    float ex = (j < 7) ? __expf(v - m) : 0.f;
    float s = ex;
#pragma unroll
    for (int off = 1; off < 8; off <<= 1)
        s += __shfl_xor_sync(~0u, s, off);
    if (g == 0 && j < 7)
        out[(size_t)w * NCLS + j] = v - m - logf(s);
}

// ---------------- launch ------------------------------------------------------

extern "C" void kernel_launch(void* const* d_in, const int* in_sizes, int n_in,
                              void* d_out, int out_size) {
    const float* x   = (const float*)d_in[0];
    const int*   ei  = (const int*)  d_in[1];
    const float* hw  = (const float*)d_in[2];
    const float* W1  = (const float*)d_in[3];
    const float* att = (const float*)d_in[4];
    const float* b1  = (const float*)d_in[5];
    const float* W2  = (const float*)d_in[6];
    const float* b2  = (const float*)d_in[7];
    float* out = (float*)d_out;

    const int* row = ei;        // edge_index[0]
    const int* col = ei + EE;   // edge_index[1]

    const int EB2 = (EE / 2 + 255) / 256;     // 3125 (2 edges/thread)
    const int WB  = (NN * 32 + 255) / 256;    // 6250 (warp-per-segment kernels)

    k_init<<<NB, 256>>>();
    k_count<<<EB2, 256>>>(row, col);
    k_bsum_scan<<<NB, 256>>>();
    k_gemm1<<<(NN + GM_BM - 1) / GM_BM, 256>>>(x, W1, att);   // launch #4 -> ncu
    k_scanfin<<<NB, 256>>>(hw);
    k_scatter<<<EB2, 256>>>(row, col);
    k_den<<<WB, 256>>>(hw);
    k_prop1<<<WB, 256>>>();
    k_prop2<<<WB, 256>>>(b1, W2);
    k2_prop1<<<WB, 256>>>();
    k2_prop2<<<WB, 256>>>(b2, out);
}

// round 7
// speedup vs baseline: 4.2712x; 1.1651x over previous
#include <cuda_runtime.h>
#include <cuda_fp16.h>
#include <mma.h>
#include <math.h>

using namespace nvcuda;

#define NN   50000
#define EE   1600000
#define FIN  512
#define HH   8
#define HID  64
#define NCLS 7
#define NEG_SLOPE 0.2f
#define NB   196            // (NN+255)/256

// ---------------- scratch (device globals) -----------------------------------
__device__ int     g_cntR[NN], g_cntC[NN];
__device__ int     g_offR[NN + 1], g_offC[NN + 1];
__device__ int     g_curR[NN], g_curC[NN];
__device__ int     g_bsumR[256], g_bsumC[256], g_bprefR[256], g_bprefC[256];
__device__ int     g_ctr;
__device__ int     g_sortedR[EE];   // edges sorted by col: stores row id
__device__ int     g_sortedC[EE];   // edges sorted by row: stores col id
__device__ __half2 g_xh_h [NN * 32];   // x @ W1, fp16 (32 half2 per node)
__device__ __half2 g_oute_h[NN * 32];  // hyperedge features, fp16
__device__ float   g_sird[NN * 16];    // interleaved (si, rden) per (node, head)
__device__ float   g_sj  [NN * HH];
__device__ float   g_Dinv[NN];
__device__ float   g_Binv[NN];
__device__ float   g_xh2 [NN * 8];     // h1 @ W2, padded 7->8
__device__ float   g_oute2[NN * 8];

__device__ __forceinline__ float lrelu(float a) { return a > 0.f ? a : NEG_SLOPE * a; }

// cp.async 16B with zero-fill predicate
__device__ __forceinline__ void cp16(void* s, const void* g, bool pred) {
    unsigned sa = (unsigned)__cvta_generic_to_shared(s);
    int sz = pred ? 16 : 0;
    asm volatile("cp.async.cg.shared.global [%0], [%1], 16, %2;"
                 :: "r"(sa), "l"(g), "r"(sz));
}
__device__ __forceinline__ void cp_commit() {
    asm volatile("cp.async.commit_group;");
}

// ---------------- sort construction ------------------------------------------

__global__ void k_init() {
    int i = blockIdx.x * blockDim.x + threadIdx.x;
    if (i < NN) { g_cntR[i] = 0; g_cntC[i] = 0; }
    if (i == 0) { g_offR[NN] = EE; g_offC[NN] = EE; g_ctr = 0; }
}

__global__ void k_count(const int* __restrict__ row, const int* __restrict__ col) {
    int e = (blockIdx.x * blockDim.x + threadIdx.x) * 2;
    if (e >= EE) return;
    int2 r = *(const int2*)&row[e];
    int2 c = *(const int2*)&col[e];
    atomicAdd(&g_cntR[r.x], 1);
    atomicAdd(&g_cntC[c.x], 1);
    atomicAdd(&g_cntR[r.y], 1);
    atomicAdd(&g_cntC[c.y], 1);
}

// fused: per-block partial sums + (last block) scan of the 196 partials
__global__ void k_bsum_scan() {
    int t = threadIdx.x, b = blockIdx.x;
    int i = b * 256 + t;
    int vr = (i < NN) ? g_cntR[i] : 0;
    int vc = (i < NN) ? g_cntC[i] : 0;
    __shared__ int sr[8], sc[8];
    __shared__ int s_last;
#pragma unroll
    for (int o = 16; o; o >>= 1) {
        vr += __shfl_down_sync(~0u, vr, o);
        vc += __shfl_down_sync(~0u, vc, o);
    }
    if ((t & 31) == 0) { sr[t >> 5] = vr; sc[t >> 5] = vc; }
    __syncthreads();
    if (t < 8) {
        vr = sr[t]; vc = sc[t];
#pragma unroll
        for (int o = 4; o; o >>= 1) {
            vr += __shfl_down_sync(0xffu, vr, o);
            vc += __shfl_down_sync(0xffu, vc, o);
        }
        if (t == 0) { g_bsumR[b] = vr; g_bsumC[b] = vc; }
    }
    __threadfence();
    if (t == 0) s_last = (atomicAdd(&g_ctr, 1) == gridDim.x - 1);
    __syncthreads();
    if (!s_last) return;
    __shared__ int s[256];
    int v = (t < NB) ? g_bsumR[t] : 0;
    s[t] = v; __syncthreads();
    for (int d = 1; d < 256; d <<= 1) {
        int x = (t >= d) ? s[t - d] : 0; __syncthreads();
        s[t] += x; __syncthreads();
    }
    g_bprefR[t] = s[t] - v;
    __syncthreads();
    int vc2 = (t < NB) ? g_bsumC[t] : 0;
    s[t] = vc2; __syncthreads();
    for (int d = 1; d < 256; d <<= 1) {
        int x = (t >= d) ? s[t - d] : 0; __syncthreads();
        s[t] += x; __syncthreads();
    }
    g_bprefC[t] = s[t] - vc2;
}

__global__ void k_scanfin(const float* __restrict__ hw) {
    __shared__ int s[256];
    int t = threadIdx.x, b = blockIdx.x;
    int i = b * 256 + t;
    int v = (i < NN) ? g_cntR[i] : 0;
    s[t] = v; __syncthreads();
    for (int d = 1; d < 256; d <<= 1) {
        int x = (t >= d) ? s[t - d] : 0; __syncthreads();
        s[t] += x; __syncthreads();
    }
    if (i < NN) {
        int off = g_bprefR[b] + s[t] - v;
        g_offR[i] = off; g_curR[i] = off;
    }
    __syncthreads();
    int vc = (i < NN) ? g_cntC[i] : 0;
    s[t] = vc; __syncthreads();
    for (int d = 1; d < 256; d <<= 1) {
        int x = (t >= d) ? s[t - d] : 0; __syncthreads();
        s[t] += x; __syncthreads();
    }
    if (i < NN) {
        int off = g_bprefC[b] + s[t] - vc;
        g_offC[i] = off; g_curC[i] = off;
        g_Binv[i] = vc > 0 ? __ldg(&hw[i]) / (float)vc : 0.f;
    }
}

__global__ void k_scatter(const int* __restrict__ row, const int* __restrict__ col) {
    int e = (blockIdx.x * blockDim.x + threadIdx.x) * 2;
    if (e >= EE) return;
    int2 r = *(const int2*)&row[e];
    int2 c = *(const int2*)&col[e];
    int pc0 = atomicAdd(&g_curC[c.x], 1);
    int pr0 = atomicAdd(&g_curR[r.x], 1);
    int pc1 = atomicAdd(&g_curC[c.y], 1);
    int pr1 = atomicAdd(&g_curR[r.y], 1);
    g_sortedR[pc0] = r.x;
    g_sortedC[pr0] = c.x;
    g_sortedR[pc1] = r.y;
    g_sortedC[pr1] = c.y;
}

// ------- GEMM1: tf32 wmma + cp.async double-buffer + fused scores/fp16 -------
// smem: 2 stages x (A 128x32 = 4096 f, B 32x64 = 2048 f) = 12288 f = 48KB
#define GM_BM 128
#define GM_BK 32
__global__ void k_gemm1(const float* __restrict__ X, const float* __restrict__ W,
                        const float* __restrict__ att) {
    __shared__ float smem[12288];
    int tid = threadIdx.x;
    int warp = tid >> 5;
    int wm = warp >> 1;
    int wn = warp & 1;
    int bm = blockIdx.x * GM_BM;

    // per-thread load coordinates
    int amل = 0; (void)amل;
    wmma::fragment<wmma::accumulator, 16, 16, 8, float> acc[2][2];
#pragma unroll
    for (int i = 0; i < 2; i++)
#pragma unroll
        for (int j = 0; j < 2; j++) wmma::fill_fragment(acc[i][j], 0.f);

    // prefetch stage 0
    {
        float* sA = &smem[0];
        float* sB = &smem[4096];
#pragma unroll
        for (int l = 0; l < 4; l++) {
            int p = tid + l * 256, m = p >> 3, k4 = (p & 7) << 2;
            cp16(&sA[m * GM_BK + k4], &X[(size_t)(bm + m) * FIN + k4], (bm + m) < NN);
        }
#pragma unroll
        for (int l = 0; l < 2; l++) {
            int p = tid + l * 256, k = p >> 4, n4 = (p & 15) << 2;
            cp16(&sB[k * 64 + n4], &W[(size_t)k * 64 + n4], true);
        }
        cp_commit();
    }

    int buf = 0;
    for (int k0 = 0; k0 < FIN; k0 += GM_BK) {
        int knext = k0 + GM_BK;
        if (knext < FIN) {             // prefetch next stage into buf^1
            float* sA = &smem[(buf ^ 1) * 6144];
            float* sB = &smem[(buf ^ 1) * 6144 + 4096];
#pragma unroll
            for (int l = 0; l < 4; l++) {
                int p = tid + l * 256, m = p >> 3, k4 = (p & 7) << 2;
                cp16(&sA[m * GM_BK + k4], &X[(size_t)(bm + m) * FIN + knext + k4],
                     (bm + m) < NN);
            }
#pragma unroll
            for (int l = 0; l < 2; l++) {
                int p = tid + l * 256, k = p >> 4, n4 = (p & 15) << 2;
                cp16(&sB[k * 64 + n4], &W[(size_t)(knext + k) * 64 + n4], true);
            }
            cp_commit();
            asm volatile("cp.async.wait_group 1;");
        } else {
            asm volatile("cp.async.wait_group 0;");
        }
        __syncthreads();
        const float* sA = &smem[buf * 6144];
        const float* sB = &smem[buf * 6144 + 4096];
#pragma unroll
        for (int kk = 0; kk < GM_BK; kk += 8) {
            wmma::fragment<wmma::matrix_a, 16, 16, 8, wmma::precision::tf32, wmma::row_major> a[2];
            wmma::fragment<wmma::matrix_b, 16, 16, 8, wmma::precision::tf32, wmma::row_major> b[2];
#pragma unroll
            for (int i = 0; i < 2; i++)
                wmma::load_matrix_sync(a[i], &sA[(wm * 32 + i * 16) * GM_BK + kk], GM_BK);
#pragma unroll
            for (int j = 0; j < 2; j++)
                wmma::load_matrix_sync(b[j], &sB[kk * 64 + wn * 32 + j * 16], 64);
#pragma unroll
            for (int i = 0; i < 2; i++)
#pragma unroll
                for (int j = 0; j < 2; j++)
                    wmma::mma_sync(acc[i][j], a[i], b[j], acc[i][j]);
        }
        __syncthreads();
        buf ^= 1;
    }

    // epilogue: C through smem (all cp.async drained; reuse everything)
    float* sC = smem;                        // 128*64
#pragma unroll
    for (int i = 0; i < 2; i++)
#pragma unroll
        for (int j = 0; j < 2; j++)
            wmma::store_matrix_sync(&sC[(wm * 32 + i * 16) * 64 + wn * 32 + j * 16],
                                    acc[i][j], 64, wmma::mem_row_major);
    __syncthreads();
    // fused scores: si -> g_sird[.x], sj -> g_sj
#pragma unroll
    for (int l = 0; l < 4; l++) {
        int p = tid + l * 256;
        int m = p >> 3, h = p & 7;
        if (bm + m < NN) {
            const float* xr = &sC[m * 64 + h * 8];
            float si = 0.f, sj = 0.f;
#pragma unroll
            for (int c = 0; c < 8; c++) {
                float v = xr[c];
                si += v * __ldg(&att[h * 16 + c]);
                sj += v * __ldg(&att[h * 16 + 8 + c]);
            }
            g_sird[((bm + m) * 8 + h) * 2] = si;
            g_sj[(bm + m) * 8 + h] = sj;
        }
    }
    // fp16 feature store: 4096 half2, 16 per thread
#pragma unroll
    for (int l = 0; l < 16; l++) {
        int p = tid + l * 256;
        int m = p >> 5, f2 = p & 31;
        if (bm + m < NN)
            g_xh_h[(size_t)(bm + m) * 32 + f2] =
                __floats2half2_rn(sC[m * 64 + f2 * 2], sC[m * 64 + f2 * 2 + 1]);
    }
}

// ---------------- denominator + Dinv (warp per node, by-row CSR) --------------
__global__ void k_den(const float* __restrict__ hw) {
    int w = (blockIdx.x * blockDim.x + threadIdx.x) >> 5;
    if (w >= NN) return;
    int lane = threadIdx.x & 31;
    int g = lane >> 3, h = lane & 7;
    int start = g_offR[w], end = g_offR[w + 1];
    float si_h = g_sird[(w * 8 + h) * 2];
    float den = 0.f, Dacc = 0.f;
    int i = start + g;
    for (; i + 4 < end; i += 8) {
        int c0 = g_sortedC[i];
        int c1 = g_sortedC[i + 4];
        float sj0 = __ldg(&g_sj[c0 * 8 + h]);
        float sj1 = __ldg(&g_sj[c1 * 8 + h]);
        den += __expf(lrelu(si_h + sj0)) + __expf(lrelu(si_h + sj1));
        if (h == 0) Dacc += __ldg(&hw[c0]) + __ldg(&hw[c1]);
    }
    if (i < end) {
        int c0 = g_sortedC[i];
        den += __expf(lrelu(si_h + __ldg(&g_sj[c0 * 8 + h])));
        if (h == 0) Dacc += __ldg(&hw[c0]);
    }
    den += __shfl_xor_sync(~0u, den, 8);
    den += __shfl_xor_sync(~0u, den, 16);
    Dacc += __shfl_xor_sync(~0u, Dacc, 8);
    Dacc += __shfl_xor_sync(~0u, Dacc, 16);
    if (g == 0) g_sird[(w * 8 + h) * 2 + 1] = 1.0f / (den + 1e-16f);
    if (lane == 0) g_Dinv[w] = Dacc > 0.f ? 1.0f / Dacc : 0.f;
}

// ---------------- prop1: nodes -> hyperedges (warp per hyperedge, fp16) -------
__global__ void k_prop1() {
    int w = (blockIdx.x * blockDim.x + threadIdx.x) >> 5;
    if (w >= NN) return;
    int lane = threadIdx.x & 31;
    int h = lane >> 2;
    int start = g_offC[w], end = g_offC[w + 1];
    float sj_h = g_sj[w * 8 + h];
    float binv = g_Binv[w];
    float ax = 0.f, ay = 0.f;
    int i = start;
    for (; i + 3 < end; i += 4) {
        int r0 = g_sortedR[i], r1 = g_sortedR[i + 1];
        int r2 = g_sortedR[i + 2], r3 = g_sortedR[i + 3];
        float2 sr0 = *(const float2*)&g_sird[(r0 * 8 + h) * 2];
        float2 sr1 = *(const float2*)&g_sird[(r1 * 8 + h) * 2];
        float2 sr2 = *(const float2*)&g_sird[(r2 * 8 + h) * 2];
        float2 sr3 = *(const float2*)&g_sird[(r3 * 8 + h) * 2];
        float2 f0 = __half22float2(g_xh_h[(size_t)r0 * 32 + lane]);
        float2 f1 = __half22float2(g_xh_h[(size_t)r1 * 32 + lane]);
        float2 f2 = __half22float2(g_xh_h[(size_t)r2 * 32 + lane]);
        float2 f3 = __half22float2(g_xh_h[(size_t)r3 * 32 + lane]);
        float w0 = __expf(lrelu(sr0.x + sj_h)) * sr0.y;
        float w1 = __expf(lrelu(sr1.x + sj_h)) * sr1.y;
        float w2 = __expf(lrelu(sr2.x + sj_h)) * sr2.y;
        float w3 = __expf(lrelu(sr3.x + sj_h)) * sr3.y;
        ax += w0 * f0.x + w1 * f1.x + w2 * f2.x + w3 * f3.x;
        ay += w0 * f0.y + w1 * f1.y + w2 * f2.y + w3 * f3.y;
    }
    for (; i < end; i++) {
        int r0 = g_sortedR[i];
        float2 sr0 = *(const float2*)&g_sird[(r0 * 8 + h) * 2];
        float2 f0 = __half22float2(g_xh_h[(size_t)r0 * 32 + lane]);
        float w0 = __expf(lrelu(sr0.x + sj_h)) * sr0.y;
        ax += w0 * f0.x; ay += w0 * f0.y;
    }
    g_oute_h[(size_t)w * 32 + lane] = __floats2half2_rn(ax * binv, ay * binv);
}

// ------- prop2 (fp16 gather) + bias + ELU + fused gemm2 (h1 never stored) -----
__global__ void k_prop2(const float* __restrict__ b1, const float* __restrict__ W2) {
    __shared__ float sW[448];
    for (int i = threadIdx.x; i < 448; i += 256) sW[i] = W2[i];
    __syncthreads();
    int w = (blockIdx.x * blockDim.x + threadIdx.x) >> 5;
    if (w >= NN) return;
    int lane = threadIdx.x & 31;
    int h = lane >> 2;
    int start = g_offR[w], end = g_offR[w + 1];
    float2 sr = *(const float2*)&g_sird[(w * 8 + h) * 2];
    float si_h = sr.x, rd_h = sr.y;
    float dinv = g_Dinv[w];
    float ax = 0.f, ay = 0.f;
    int i = start;
    for (; i + 3 < end; i += 4) {
        int c0 = g_sortedC[i], c1 = g_sortedC[i + 1];
        int c2 = g_sortedC[i + 2], c3 = g_sortedC[i + 3];
        float sj0 = __ldg(&g_sj[c0 * 8 + h]), sj1 = __ldg(&g_sj[c1 * 8 + h]);
        float sj2 = __ldg(&g_sj[c2 * 8 + h]), sj3 = __ldg(&g_sj[c3 * 8 + h]);
        float2 f0 = __half22float2(g_oute_h[(size_t)c0 * 32 + lane]);
        float2 f1 = __half22float2(g_oute_h[(size_t)c1 * 32 + lane]);
        float2 f2 = __half22float2(g_oute_h[(size_t)c2 * 32 + lane]);
        float2 f3 = __half22float2(g_oute_h[(size_t)c3 * 32 + lane]);
        float w0 = __expf(lrelu(si_h + sj0)) * rd_h;
        float w1 = __expf(lrelu(si_h + sj1)) * rd_h;
        float w2 = __expf(lrelu(si_h + sj2)) * rd_h;
        float w3 = __expf(lrelu(si_h + sj3)) * rd_h;
        ax += w0 * f0.x + w1 * f1.x + w2 * f2.x + w3 * f3.x;
        ay += w0 * f0.y + w1 * f1.y + w2 * f2.y + w3 * f3.y;
    }
    for (; i < end; i++) {
        int c0 = g_sortedC[i];
        float sj0 = __ldg(&g_sj[c0 * 8 + h]);
        float2 f0 = __half22float2(g_oute_h[(size_t)c0 * 32 + lane]);
        float w0 = __expf(lrelu(si_h + sj0)) * rd_h;
        ax += w0 * f0.x; ay += w0 * f0.y;
    }
    float vx = ax * dinv + __ldg(&b1[lane * 2]);
    float vy = ay * dinv + __ldg(&b1[lane * 2 + 1]);
    vx = vx > 0.f ? vx : expm1f(vx);
    vy = vy > 0.f ? vy : expm1f(vy);
    float a7[7];
#pragma unroll
    for (int j = 0; j < 7; j++)
        a7[j] = vx * sW[(lane * 2) * 7 + j] + vy * sW[(lane * 2 + 1) * 7 + j];
#pragma unroll
    for (int off = 16; off; off >>= 1)
#pragma unroll
        for (int j = 0; j < 7; j++)
            a7[j] += __shfl_xor_sync(~0u, a7[j], off);
    if (lane == 0) {
        float4* o = (float4*)&g_xh2[w * 8];
        o[0] = make_float4(a7[0], a7[1], a7[2], a7[3]);
        o[1] = make_float4(a7[4], a7[5], a7[6], 0.f);
    }
}

// ---------------- layer-2 propagation (warp per segment) ----------------------
__global__ void k2_prop1() {
    int w = (blockIdx.x * blockDim.x + threadIdx.x) >> 5;
    if (w >= NN) return;
    int lane = threadIdx.x & 31;
    int g = lane >> 3, j = lane & 7;
    int start = g_offC[w], end = g_offC[w + 1];
    float acc = 0.f;
    int i = start + g;
    for (; i + 4 < end; i += 8) {
        int r0 = g_sortedR[i], r1 = g_sortedR[i + 4];
        acc += __ldg(&g_xh2[r0 * 8 + j]) + __ldg(&g_xh2[r1 * 8 + j]);
    }
    if (i < end) acc += __ldg(&g_xh2[g_sortedR[i] * 8 + j]);
    acc += __shfl_xor_sync(~0u, acc, 8);
    acc += __shfl_xor_sync(~0u, acc, 16);
    if (g == 0) g_oute2[w * 8 + j] = acc * g_Binv[w];
}

// k2_prop2 + fused log_softmax
__global__ void k2_prop2(const float* __restrict__ b2, float* __restrict__ out) {
    int w = (blockIdx.x * blockDim.x + threadIdx.x) >> 5;
    if (w >= NN) return;
    int lane = threadIdx.x & 31;
    int g = lane >> 3, j = lane & 7;
    int start = g_offR[w], end = g_offR[w + 1];
    float acc = 0.f;
    int i = start + g;
    for (; i + 4 < end; i += 8) {
        int c0 = g_sortedC[i], c1 = g_sortedC[i + 4];
        acc += __ldg(&g_oute2[c0 * 8 + j]) + __ldg(&g_oute2[c1 * 8 + j]);
    }
    if (i < end) acc += __ldg(&g_oute2[g_sortedC[i] * 8 + j]);
    acc += __shfl_xor_sync(~0u, acc, 8);
    acc += __shfl_xor_sync(~0u, acc, 16);
    float v = (j < 7) ? acc * g_Dinv[w] + __ldg(&b2[j]) : -1e30f;
    float m = v;
#pragma unroll
    for (int off = 1; off < 8; off <<= 1)
        m = fmaxf(m, __shfl_xor_sync(~0u, m, off));
    float ex = (j < 7) ? __expf(v - m) : 0.f;
    float s = ex;
#pragma unroll
    for (int off = 1; off < 8; off <<= 1)
        s += __shfl_xor_sync(~0u, s, off);
    if (g == 0 && j < 7)
        out[(size_t)w * NCLS + j] = v - m - logf(s);
}

// ---------------- launch ------------------------------------------------------

extern "C" void kernel_launch(void* const* d_in, const int* in_sizes, int n_in,
                              void* d_out, int out_size) {
    const float* x   = (const float*)d_in[0];
    const int*   ei  = (const int*)  d_in[1];
    const float* hw  = (const float*)d_in[2];
    const float* W1  = (const float*)d_in[3];
    const float* att = (const float*)d_in[4];
    const float* b1  = (const float*)d_in[5];
    const float* W2  = (const float*)d_in[6];
    const float* b2  = (const float*)d_in[7];
    float* out = (float*)d_out;

    const int* row = ei;        // edge_index[0]
    const int* col = ei + EE;   // edge_index[1]

    const int EB2 = (EE / 2 + 255) / 256;     // 3125 (2 edges/thread)
    const int WB  = (NN * 32 + 255) / 256;    // 6250 (warp-per-segment kernels)

    k_init<<<NB, 256>>>();
    k_count<<<EB2, 256>>>(row, col);
    k_bsum_scan<<<NB, 256>>>();
    k_gemm1<<<(NN + GM_BM - 1) / GM_BM, 256>>>(x, W1, att);   // launch #4 -> ncu
    k_scanfin<<<NB, 256>>>(hw);
    k_scatter<<<EB2, 256>>>(row, col);
    k_den<<<WB, 256>>>(hw);
    k_prop1<<<WB, 256>>>();
    k_prop2<<<WB, 256>>>(b1, W2);
    k2_prop1<<<WB, 256>>>();
    k2_prop2<<<WB, 256>>>(b2, out);
}

// round 8
// speedup vs baseline: 4.5551x; 1.0665x over previous
#include <cuda_runtime.h>
#include <cuda_fp16.h>
#include <mma.h>
#include <math.h>

using namespace nvcuda;

#define NN   50000
#define EE   1600000
#define FIN  512
#define HH   8
#define HID  64
#define NCLS 7
#define NEG_SLOPE 0.2f
#define NB   196            // (NN+255)/256

// ---------------- scratch (device globals) -----------------------------------
__device__ int     g_cntR[NN], g_cntC[NN];
__device__ int     g_offR[NN + 1], g_offC[NN + 1];
__device__ int     g_curR[NN], g_curC[NN];
__device__ int     g_bsumR[256], g_bsumC[256], g_bprefR[256], g_bprefC[256];
__device__ int     g_ctr;
__device__ int     g_sortedR[EE];   // edges sorted by col: stores row id
__device__ int     g_sortedC[EE];   // edges sorted by row: stores col id
__device__ __half2 g_xh_h [NN * 32];   // x @ W1, fp16 (32 half2 per node)
__device__ __half2 g_oute_h[NN * 32];  // hyperedge features, fp16
__device__ float   g_sird[NN * 16];    // interleaved (si, rden) per (node, head)
__device__ float   g_sj  [NN * HH];
__device__ float   g_Dinv[NN];
__device__ float   g_Binv[NN];
__device__ float   g_xh2 [NN * 8];     // h1 @ W2, padded 7->8
__device__ float   g_oute2[NN * 8];

__device__ __forceinline__ float lrelu(float a) { return a > 0.f ? a : NEG_SLOPE * a; }

// cp.async 16B with zero-fill predicate
__device__ __forceinline__ void cp16(void* s, const void* g, bool pred) {
    unsigned sa = (unsigned)__cvta_generic_to_shared(s);
    int sz = pred ? 16 : 0;
    asm volatile("cp.async.cg.shared.global [%0], [%1], 16, %2;"
                 :: "r"(sa), "l"(g), "r"(sz));
}
__device__ __forceinline__ void cp_commit() {
    asm volatile("cp.async.commit_group;");
}

// ---------------- sort construction ------------------------------------------

__global__ void k_init() {
    int i = blockIdx.x * blockDim.x + threadIdx.x;
    if (i < NN) { g_cntR[i] = 0; g_cntC[i] = 0; }
    if (i == 0) { g_offR[NN] = EE; g_offC[NN] = EE; g_ctr = 0; }
}

__global__ void k_count(const int* __restrict__ row, const int* __restrict__ col) {
    int e = (blockIdx.x * blockDim.x + threadIdx.x) * 2;
    if (e >= EE) return;
    int2 r = *(const int2*)&row[e];
    int2 c = *(const int2*)&col[e];
    atomicAdd(&g_cntR[r.x], 1);
    atomicAdd(&g_cntC[c.x], 1);
    atomicAdd(&g_cntR[r.y], 1);
    atomicAdd(&g_cntC[c.y], 1);
}

// fused: per-block partial sums + (last block) scan of the 196 partials
__global__ void k_bsum_scan() {
    int t = threadIdx.x, b = blockIdx.x;
    int i = b * 256 + t;
    int vr = (i < NN) ? g_cntR[i] : 0;
    int vc = (i < NN) ? g_cntC[i] : 0;
    __shared__ int sr[8], sc[8];
    __shared__ int s_last;
#pragma unroll
    for (int o = 16; o; o >>= 1) {
        vr += __shfl_down_sync(~0u, vr, o);
        vc += __shfl_down_sync(~0u, vc, o);
    }
    if ((t & 31) == 0) { sr[t >> 5] = vr; sc[t >> 5] = vc; }
    __syncthreads();
    if (t < 8) {
        vr = sr[t]; vc = sc[t];
#pragma unroll
        for (int o = 4; o; o >>= 1) {
            vr += __shfl_down_sync(0xffu, vr, o);
            vc += __shfl_down_sync(0xffu, vc, o);
        }
        if (t == 0) { g_bsumR[b] = vr; g_bsumC[b] = vc; }
    }
    __threadfence();
    if (t == 0) s_last = (atomicAdd(&g_ctr, 1) == gridDim.x - 1);
    __syncthreads();
    if (!s_last) return;
    __shared__ int s[256];
    int v = (t < NB) ? g_bsumR[t] : 0;
    s[t] = v; __syncthreads();
    for (int d = 1; d < 256; d <<= 1) {
        int x = (t >= d) ? s[t - d] : 0; __syncthreads();
        s[t] += x; __syncthreads();
    }
    g_bprefR[t] = s[t] - v;
    __syncthreads();
    int vc2 = (t < NB) ? g_bsumC[t] : 0;
    s[t] = vc2; __syncthreads();
    for (int d = 1; d < 256; d <<= 1) {
        int x = (t >= d) ? s[t - d] : 0; __syncthreads();
        s[t] += x; __syncthreads();
    }
    g_bprefC[t] = s[t] - vc2;
}

__global__ void k_scanfin(const float* __restrict__ hw) {
    __shared__ int s[256];
    int t = threadIdx.x, b = blockIdx.x;
    int i = b * 256 + t;
    int v = (i < NN) ? g_cntR[i] : 0;
    s[t] = v; __syncthreads();
    for (int d = 1; d < 256; d <<= 1) {
        int x = (t >= d) ? s[t - d] : 0; __syncthreads();
        s[t] += x; __syncthreads();
    }
    if (i < NN) {
        int off = g_bprefR[b] + s[t] - v;
        g_offR[i] = off; g_curR[i] = off;
    }
    __syncthreads();
    int vc = (i < NN) ? g_cntC[i] : 0;
    s[t] = vc; __syncthreads();
    for (int d = 1; d < 256; d <<= 1) {
        int x = (t >= d) ? s[t - d] : 0; __syncthreads();
        s[t] += x; __syncthreads();
    }
    if (i < NN) {
        int off = g_bprefC[b] + s[t] - vc;
        g_offC[i] = off; g_curC[i] = off;
        g_Binv[i] = vc > 0 ? __ldg(&hw[i]) / (float)vc : 0.f;
    }
}

__global__ void k_scatter(const int* __restrict__ row, const int* __restrict__ col) {
    int e = (blockIdx.x * blockDim.x + threadIdx.x) * 2;
    if (e >= EE) return;
    int2 r = *(const int2*)&row[e];
    int2 c = *(const int2*)&col[e];
    int pc0 = atomicAdd(&g_curC[c.x], 1);
    int pr0 = atomicAdd(&g_curR[r.x], 1);
    int pc1 = atomicAdd(&g_curC[c.y], 1);
    int pr1 = atomicAdd(&g_curR[r.y], 1);
    g_sortedR[pc0] = r.x;
    g_sortedC[pr0] = c.x;
    g_sortedR[pc1] = r.y;
    g_sortedC[pr1] = c.y;
}

// ------- GEMM1: tf32 wmma, 3-stage cp.async, padded (conflict-free) smem ------
// stage = A 128x36 (pad) + B 32x68 (pad) = 6784 floats = 26.5KB; 3 stages = 81KB
#define GM_BM 128
#define GM_BK 32
#define LDA 36
#define LDB 68
#define LDC 68
#define STG 6784
__global__ void k_gemm1(const float* __restrict__ X, const float* __restrict__ W,
                        const float* __restrict__ att) {
    extern __shared__ float smem[];
    int tid = threadIdx.x;
    int warp = tid >> 5;
    int wm = warp >> 1;
    int wn = warp & 1;
    int bm = blockIdx.x * GM_BM;

    wmma::fragment<wmma::accumulator, 16, 16, 8, float> acc[2][2];
#pragma unroll
    for (int i = 0; i < 2; i++)
#pragma unroll
        for (int j = 0; j < 2; j++) wmma::fill_fragment(acc[i][j], 0.f);

    // prefetch stages 0, 1
#pragma unroll
    for (int st = 0; st < 2; st++) {
        float* sA = &smem[st * STG];
        float* sB = &smem[st * STG + GM_BM * LDA];
        int kb = st * GM_BK;
#pragma unroll
        for (int l = 0; l < 4; l++) {
            int p = tid + l * 256, m = p >> 3, k4 = (p & 7) << 2;
            cp16(&sA[m * LDA + k4], &X[(size_t)(bm + m) * FIN + kb + k4], (bm + m) < NN);
        }
#pragma unroll
        for (int l = 0; l < 2; l++) {
            int p = tid + l * 256, k = p >> 4, n4 = (p & 15) << 2;
            cp16(&sB[k * LDB + n4], &W[(size_t)(kb + k) * 64 + n4], true);
        }
        cp_commit();
    }

    int buf = 0;
    for (int k0 = 0; k0 < FIN; k0 += GM_BK) {
        asm volatile("cp.async.wait_group 1;");
        __syncthreads();
        int kpre = k0 + 2 * GM_BK;
        if (kpre < FIN) {              // prefetch stage k+2 into slot (buf+2)%3
            int slot = buf + 2; if (slot >= 3) slot -= 3;
            float* sA = &smem[slot * STG];
            float* sB = &smem[slot * STG + GM_BM * LDA];
#pragma unroll
            for (int l = 0; l < 4; l++) {
                int p = tid + l * 256, m = p >> 3, k4 = (p & 7) << 2;
                cp16(&sA[m * LDA + k4], &X[(size_t)(bm + m) * FIN + kpre + k4],
                     (bm + m) < NN);
            }
#pragma unroll
            for (int l = 0; l < 2; l++) {
                int p = tid + l * 256, k = p >> 4, n4 = (p & 15) << 2;
                cp16(&sB[k * LDB + n4], &W[(size_t)(kpre + k) * 64 + n4], true);
            }
        }
        cp_commit();                   // always commit (keeps group count uniform)
        const float* sA = &smem[buf * STG];
        const float* sB = &smem[buf * STG + GM_BM * LDA];
#pragma unroll
        for (int kk = 0; kk < GM_BK; kk += 8) {
            wmma::fragment<wmma::matrix_a, 16, 16, 8, wmma::precision::tf32, wmma::row_major> a[2];
            wmma::fragment<wmma::matrix_b, 16, 16, 8, wmma::precision::tf32, wmma::row_major> b[2];
#pragma unroll
            for (int i = 0; i < 2; i++)
                wmma::load_matrix_sync(a[i], &sA[(wm * 32 + i * 16) * LDA + kk], LDA);
#pragma unroll
            for (int j = 0; j < 2; j++)
                wmma::load_matrix_sync(b[j], &sB[kk * LDB + wn * 32 + j * 16], LDB);
#pragma unroll
            for (int i = 0; i < 2; i++)
#pragma unroll
                for (int j = 0; j < 2; j++)
                    wmma::mma_sync(acc[i][j], a[i], b[j], acc[i][j]);
        }
        buf++; if (buf >= 3) buf -= 3;
    }
    __syncthreads();                   // drain before reusing smem for C

    float* sC = smem;                  // 128 x 68 (padded)
#pragma unroll
    for (int i = 0; i < 2; i++)
#pragma unroll
        for (int j = 0; j < 2; j++)
            wmma::store_matrix_sync(&sC[(wm * 32 + i * 16) * LDC + wn * 32 + j * 16],
                                    acc[i][j], LDC, wmma::mem_row_major);
    __syncthreads();
    // fused scores: si -> g_sird[.x], sj -> g_sj
#pragma unroll
    for (int l = 0; l < 4; l++) {
        int p = tid + l * 256;
        int m = p >> 3, h = p & 7;
        if (bm + m < NN) {
            const float* xr = &sC[m * LDC + h * 8];
            float si = 0.f, sj = 0.f;
#pragma unroll
            for (int c = 0; c < 8; c++) {
                float v = xr[c];
                si += v * __ldg(&att[h * 16 + c]);
                sj += v * __ldg(&att[h * 16 + 8 + c]);
            }
            g_sird[((bm + m) * 8 + h) * 2] = si;
            g_sj[(bm + m) * 8 + h] = sj;
        }
    }
    // fp16 feature store: 4096 half2, 16 per thread
#pragma unroll
    for (int l = 0; l < 16; l++) {
        int p = tid + l * 256;
        int m = p >> 5, f2 = p & 31;
        if (bm + m < NN)
            g_xh_h[(size_t)(bm + m) * 32 + f2] =
                __floats2half2_rn(sC[m * LDC + f2 * 2], sC[m * LDC + f2 * 2 + 1]);
    }
}

// ---------------- denominator + Dinv (warp per node, by-row CSR) --------------
__global__ void k_den(const float* __restrict__ hw) {
    int w = (blockIdx.x * blockDim.x + threadIdx.x) >> 5;
    if (w >= NN) return;
    int lane = threadIdx.x & 31;
    int g = lane >> 3, h = lane & 7;
    int start = g_offR[w], end = g_offR[w + 1];
    float si_h = g_sird[(w * 8 + h) * 2];
    float den = 0.f, Dacc = 0.f;
    int i = start + g;
    for (; i + 4 < end; i += 8) {
        int c0 = g_sortedC[i];
        int c1 = g_sortedC[i + 4];
        float sj0 = __ldg(&g_sj[c0 * 8 + h]);
        float sj1 = __ldg(&g_sj[c1 * 8 + h]);
        den += __expf(lrelu(si_h + sj0)) + __expf(lrelu(si_h + sj1));
        if (h == 0) Dacc += __ldg(&hw[c0]) + __ldg(&hw[c1]);
    }
    if (i < end) {
        int c0 = g_sortedC[i];
        den += __expf(lrelu(si_h + __ldg(&g_sj[c0 * 8 + h])));
        if (h == 0) Dacc += __ldg(&hw[c0]);
    }
    den += __shfl_xor_sync(~0u, den, 8);
    den += __shfl_xor_sync(~0u, den, 16);
    Dacc += __shfl_xor_sync(~0u, Dacc, 8);
    Dacc += __shfl_xor_sync(~0u, Dacc, 16);
    if (g == 0) g_sird[(w * 8 + h) * 2 + 1] = 1.0f / (den + 1e-16f);
    if (lane == 0) g_Dinv[w] = Dacc > 0.f ? 1.0f / Dacc : 0.f;
}

// ---------------- prop1: nodes -> hyperedges (warp per hyperedge, fp16) -------
__global__ void k_prop1() {
    int w = (blockIdx.x * blockDim.x + threadIdx.x) >> 5;
    if (w >= NN) return;
    int lane = threadIdx.x & 31;
    int h = lane >> 2;
    int start = g_offC[w], end = g_offC[w + 1];
    float sj_h = g_sj[w * 8 + h];
    float binv = g_Binv[w];
    float ax = 0.f, ay = 0.f;
    int i = start;
    for (; i + 3 < end; i += 4) {
        int r0 = g_sortedR[i], r1 = g_sortedR[i + 1];
        int r2 = g_sortedR[i + 2], r3 = g_sortedR[i + 3];
        float2 sr0 = *(const float2*)&g_sird[(r0 * 8 + h) * 2];
        float2 sr1 = *(const float2*)&g_sird[(r1 * 8 + h) * 2];
        float2 sr2 = *(const float2*)&g_sird[(r2 * 8 + h) * 2];
        float2 sr3 = *(const float2*)&g_sird[(r3 * 8 + h) * 2];
        float2 f0 = __half22float2(g_xh_h[(size_t)r0 * 32 + lane]);
        float2 f1 = __half22float2(g_xh_h[(size_t)r1 * 32 + lane]);
        float2 f2 = __half22float2(g_xh_h[(size_t)r2 * 32 + lane]);
        float2 f3 = __half22float2(g_xh_h[(size_t)r3 * 32 + lane]);
        float w0 = __expf(lrelu(sr0.x + sj_h)) * sr0.y;
        float w1 = __expf(lrelu(sr1.x + sj_h)) * sr1.y;
        float w2 = __expf(lrelu(sr2.x + sj_h)) * sr2.y;
        float w3 = __expf(lrelu(sr3.x + sj_h)) * sr3.y;
        ax += w0 * f0.x + w1 * f1.x + w2 * f2.x + w3 * f3.x;
        ay += w0 * f0.y + w1 * f1.y + w2 * f2.y + w3 * f3.y;
    }
    for (; i < end; i++) {
        int r0 = g_sortedR[i];
        float2 sr0 = *(const float2*)&g_sird[(r0 * 8 + h) * 2];
        float2 f0 = __half22float2(g_xh_h[(size_t)r0 * 32 + lane]);
        float w0 = __expf(lrelu(sr0.x + sj_h)) * sr0.y;
        ax += w0 * f0.x; ay += w0 * f0.y;
    }
    g_oute_h[(size_t)w * 32 + lane] = __floats2half2_rn(ax * binv, ay * binv);
}

// ------- prop2 (fp16 gather) + bias + ELU + fused gemm2 (h1 never stored) -----
__global__ void k_prop2(const float* __restrict__ b1, const float* __restrict__ W2) {
    __shared__ float sW[448];
    for (int i = threadIdx.x; i < 448; i += 256) sW[i] = W2[i];
    __syncthreads();
    int w = (blockIdx.x * blockDim.x + threadIdx.x) >> 5;
    if (w >= NN) return;
    int lane = threadIdx.x & 31;
    int h = lane >> 2;
    int start = g_offR[w], end = g_offR[w + 1];
    float2 sr = *(const float2*)&g_sird[(w * 8 + h) * 2];
    float si_h = sr.x, rd_h = sr.y;
    float dinv = g_Dinv[w];
    float ax = 0.f, ay = 0.f;
    int i = start;
    for (; i + 3 < end; i += 4) {
        int c0 = g_sortedC[i], c1 = g_sortedC[i + 1];
        int c2 = g_sortedC[i + 2], c3 = g_sortedC[i + 3];
        float sj0 = __ldg(&g_sj[c0 * 8 + h]), sj1 = __ldg(&g_sj[c1 * 8 + h]);
        float sj2 = __ldg(&g_sj[c2 * 8 + h]), sj3 = __ldg(&g_sj[c3 * 8 + h]);
        float2 f0 = __half22float2(g_oute_h[(size_t)c0 * 32 + lane]);
        float2 f1 = __half22float2(g_oute_h[(size_t)c1 * 32 + lane]);
        float2 f2 = __half22float2(g_oute_h[(size_t)c2 * 32 + lane]);
        float2 f3 = __half22float2(g_oute_h[(size_t)c3 * 32 + lane]);
        float w0 = __expf(lrelu(si_h + sj0)) * rd_h;
        float w1 = __expf(lrelu(si_h + sj1)) * rd_h;
        float w2 = __expf(lrelu(si_h + sj2)) * rd_h;
        float w3 = __expf(lrelu(si_h + sj3)) * rd_h;
        ax += w0 * f0.x + w1 * f1.x + w2 * f2.x + w3 * f3.x;
        ay += w0 * f0.y + w1 * f1.y + w2 * f2.y + w3 * f3.y;
    }
    for (; i < end; i++) {
        int c0 = g_sortedC[i];
        float sj0 = __ldg(&g_sj[c0 * 8 + h]);
        float2 f0 = __half22float2(g_oute_h[(size_t)c0 * 32 + lane]);
        float w0 = __expf(lrelu(si_h + sj0)) * rd_h;
        ax += w0 * f0.x; ay += w0 * f0.y;
    }
    float vx = ax * dinv + __ldg(&b1[lane * 2]);
    float vy = ay * dinv + __ldg(&b1[lane * 2 + 1]);
    vx = vx > 0.f ? vx : expm1f(vx);
    vy = vy > 0.f ? vy : expm1f(vy);
    float a7[7];
#pragma unroll
    for (int j = 0; j < 7; j++)
        a7[j] = vx * sW[(lane * 2) * 7 + j] + vy * sW[(lane * 2 + 1) * 7 + j];
#pragma unroll
    for (int off = 16; off; off >>= 1)
#pragma unroll
        for (int j = 0; j < 7; j++)
            a7[j] += __shfl_xor_sync(~0u, a7[j], off);
    if (lane == 0) {
        float4* o = (float4*)&g_xh2[w * 8];
        o[0] = make_float4(a7[0], a7[1], a7[2], a7[3]);
        o[1] = make_float4(a7[4], a7[5], a7[6], 0.f);
    }
}

// ---------------- layer-2 propagation (warp per segment) ----------------------
__global__ void k2_prop1() {
    int w = (blockIdx.x * blockDim.x + threadIdx.x) >> 5;
    if (w >= NN) return;
    int lane = threadIdx.x & 31;
    int g = lane >> 3, j = lane & 7;
    int start = g_offC[w], end = g_offC[w + 1];
    float acc = 0.f;
    int i = start + g;
    for (; i + 4 < end; i += 8) {
        int r0 = g_sortedR[i], r1 = g_sortedR[i + 4];
        acc += __ldg(&g_xh2[r0 * 8 + j]) + __ldg(&g_xh2[r1 * 8 + j]);
    }
    if (i < end) acc += __ldg(&g_xh2[g_sortedR[i] * 8 + j]);
    acc += __shfl_xor_sync(~0u, acc, 8);
    acc += __shfl_xor_sync(~0u, acc, 16);
    if (g == 0) g_oute2[w * 8 + j] = acc * g_Binv[w];
}

// k2_prop2 + fused log_softmax
__global__ void k2_prop2(const float* __restrict__ b2, float* __restrict__ out) {
    int w = (blockIdx.x * blockDim.x + threadIdx.x) >> 5;
    if (w >= NN) return;
    int lane = threadIdx.x & 31;
    int g = lane >> 3, j = lane & 7;
    int start = g_offR[w], end = g_offR[w + 1];
    float acc = 0.f;
    int i = start + g;
    for (; i + 4 < end; i += 8) {
        int c0 = g_sortedC[i], c1 = g_sortedC[i + 4];
        acc += __ldg(&g_oute2[c0 * 8 + j]) + __ldg(&g_oute2[c1 * 8 + j]);
    }
    if (i < end) acc += __ldg(&g_oute2[g_sortedC[i] * 8 + j]);
    acc += __shfl_xor_sync(~0u, acc, 8);
    acc += __shfl_xor_sync(~0u, acc, 16);
    float v = (j < 7) ? acc * g_Dinv[w] + __ldg(&b2[j]) : -1e30f;
    float m = v;
#pragma unroll
    for (int off = 1; off < 8; off <<= 1)
        m = fmaxf(m, __shfl_xor_sync(~0u, m, off));
    float ex = (j < 7) ? __expf(v - m) : 0.f;
    float s = ex;
#pragma unroll
    for (int off = 1; off < 8; off <<= 1)
        s += __shfl_xor_sync(~0u, s, off);
    if (g == 0 && j < 7)
        out[(size_t)w * NCLS + j] = v - m - logf(s);
}

// ---------------- launch ------------------------------------------------------

extern "C" void kernel_launch(void* const* d_in, const int* in_sizes, int n_in,
                              void* d_out, int out_size) {
    const float* x   = (const float*)d_in[0];
    const int*   ei  = (const int*)  d_in[1];
    const float* hw  = (const float*)d_in[2];
    const float* W1  = (const float*)d_in[3];
    const float* att = (const float*)d_in[4];
    const float* b1  = (const float*)d_in[5];
    const float* W2  = (const float*)d_in[6];
    const float* b2  = (const float*)d_in[7];
    float* out = (float*)d_out;

    const int* row = ei;        // edge_index[0]
    const int* col = ei + EE;   // edge_index[1]

    const int EB2 = (EE / 2 + 255) / 256;     // 3125 (2 edges/thread)
    const int WB  = (NN * 32 + 255) / 256;    // 6250 (warp-per-segment kernels)
    const int GEMM_SMEM = 3 * STG * 4;        // 81408 bytes

    cudaFuncSetAttribute(k_gemm1, cudaFuncAttributeMaxDynamicSharedMemorySize,
                         GEMM_SMEM);

    k_init<<<NB, 256>>>();
    k_count<<<EB2, 256>>>(row, col);
    k_bsum_scan<<<NB, 256>>>();
    k_gemm1<<<(NN + GM_BM - 1) / GM_BM, 256, GEMM_SMEM>>>(x, W1, att); // launch #4
    k_scanfin<<<NB, 256>>>(hw);
    k_scatter<<<EB2, 256>>>(row, col);
    k_den<<<WB, 256>>>(hw);
    k_prop1<<<WB, 256>>>();
    k_prop2<<<WB, 256>>>(b1, W2);
    k2_prop1<<<WB, 256>>>();
    k2_prop2<<<WB, 256>>>(b2, out);
}

// round 9
// speedup vs baseline: 4.6462x; 1.0200x over previous
#include <cuda_runtime.h>
#include <cuda_fp16.h>
#include <mma.h>
#include <math.h>

using namespace nvcuda;

#define NN   50000
#define EE   1600000
#define FIN  512
#define HH   8
#define HID  64
#define NCLS 7
#define NEG_SLOPE 0.2f
#define NB   196            // (NN+255)/256

// ---------------- scratch (device globals) -----------------------------------
// g_cntR/g_cntC are zero at module load and re-zeroed by k_scanfin each call
// (self-restoring), so no init kernel is needed. g_ctr likewise by k_bsum_scan.
__device__ int     g_cntR[NN], g_cntC[NN];
__device__ int     g_offR[NN + 1], g_offC[NN + 1];
__device__ int     g_curR[NN], g_curC[NN];
__device__ int     g_bsumR[256], g_bsumC[256], g_bprefR[256], g_bprefC[256];
__device__ int     g_ctr;
__device__ int     g_sortedR[EE];   // edges sorted by col: stores row id
__device__ int     g_sortedC[EE];   // edges sorted by row: stores col id
__device__ __half2 g_xh_h [NN * 32];   // x @ W1, fp16 (32 half2 per node)
__device__ __half2 g_oute_h[NN * 32];  // hyperedge features, fp16
__device__ float   g_sird[NN * 16];    // interleaved (si, rden) per (node, head)
__device__ float   g_sj  [NN * HH];
__device__ float   g_Dinv[NN];
__device__ float   g_Binv[NN];
__device__ float   g_xh2 [NN * 8];     // h1 @ W2, padded 7->8
__device__ float   g_oute2[NN * 8];

__device__ __forceinline__ float lrelu(float a) { return a > 0.f ? a : NEG_SLOPE * a; }

// cp.async 16B with zero-fill predicate
__device__ __forceinline__ void cp16(void* s, const void* g, bool pred) {
    unsigned sa = (unsigned)__cvta_generic_to_shared(s);
    int sz = pred ? 16 : 0;
    asm volatile("cp.async.cg.shared.global [%0], [%1], 16, %2;"
                 :: "r"(sa), "l"(g), "r"(sz));
}
__device__ __forceinline__ void cp_commit() {
    asm volatile("cp.async.commit_group;");
}

// ---------------- sort construction ------------------------------------------

__global__ void k_count(const int* __restrict__ row, const int* __restrict__ col) {
    int e = (blockIdx.x * blockDim.x + threadIdx.x) * 2;
    if (e >= EE) return;
    int2 r = *(const int2*)&row[e];
    int2 c = *(const int2*)&col[e];
    atomicAdd(&g_cntR[r.x], 1);
    atomicAdd(&g_cntC[c.x], 1);
    atomicAdd(&g_cntR[r.y], 1);
    atomicAdd(&g_cntC[c.y], 1);
}

// fused: per-block partial sums + (last block) scan of the 196 partials
__global__ void k_bsum_scan() {
    int t = threadIdx.x, b = blockIdx.x;
    int i = b * 256 + t;
    int vr = (i < NN) ? g_cntR[i] : 0;
    int vc = (i < NN) ? g_cntC[i] : 0;
    __shared__ int sr[8], sc[8];
    __shared__ int s_last;
#pragma unroll
    for (int o = 16; o; o >>= 1) {
        vr += __shfl_down_sync(~0u, vr, o);
        vc += __shfl_down_sync(~0u, vc, o);
    }
    if ((t & 31) == 0) { sr[t >> 5] = vr; sc[t >> 5] = vc; }
    __syncthreads();
    if (t < 8) {
        vr = sr[t]; vc = sc[t];
#pragma unroll
        for (int o = 4; o; o >>= 1) {
            vr += __shfl_down_sync(0xffu, vr, o);
            vc += __shfl_down_sync(0xffu, vc, o);
        }
        if (t == 0) { g_bsumR[b] = vr; g_bsumC[b] = vc; }
    }
    __threadfence();
    if (t == 0) s_last = (atomicAdd(&g_ctr, 1) == gridDim.x - 1);
    __syncthreads();
    if (!s_last) return;
    __shared__ int s[256];
    int v = (t < NB) ? g_bsumR[t] : 0;
    s[t] = v; __syncthreads();
    for (int d = 1; d < 256; d <<= 1) {
        int x = (t >= d) ? s[t - d] : 0; __syncthreads();
        s[t] += x; __syncthreads();
    }
    g_bprefR[t] = s[t] - v;
    __syncthreads();
    int vc2 = (t < NB) ? g_bsumC[t] : 0;
    s[t] = vc2; __syncthreads();
    for (int d = 1; d < 256; d <<= 1) {
        int x = (t >= d) ? s[t - d] : 0; __syncthreads();
        s[t] += x; __syncthreads();
    }
    g_bprefC[t] = s[t] - vc2;
    if (t == 0) g_ctr = 0;             // self-restore for next call
}

__global__ void k_scanfin(const float* __restrict__ hw) {
    __shared__ int s[256];
    int t = threadIdx.x, b = blockIdx.x;
    int i = b * 256 + t;
    if (b == 0 && t == 0) { g_offR[NN] = EE; g_offC[NN] = EE; }
    int v = (i < NN) ? g_cntR[i] : 0;
    s[t] = v; __syncthreads();
    for (int d = 1; d < 256; d <<= 1) {
        int x = (t >= d) ? s[t - d] : 0; __syncthreads();
        s[t] += x; __syncthreads();
    }
    if (i < NN) {
        int off = g_bprefR[b] + s[t] - v;
        g_offR[i] = off; g_curR[i] = off;
        g_cntR[i] = 0;                 // self-restore for next call
    }
    __syncthreads();
    int vc = (i < NN) ? g_cntC[i] : 0;
    s[t] = vc; __syncthreads();
    for (int d = 1; d < 256; d <<= 1) {
        int x = (t >= d) ? s[t - d] : 0; __syncthreads();
        s[t] += x; __syncthreads();
    }
    if (i < NN) {
        int off = g_bprefC[b] + s[t] - vc;
        g_offC[i] = off; g_curC[i] = off;
        g_Binv[i] = vc > 0 ? __ldg(&hw[i]) / (float)vc : 0.f;
        g_cntC[i] = 0;                 // self-restore for next call
    }
}

__global__ void k_scatter(const int* __restrict__ row, const int* __restrict__ col) {
    int e = (blockIdx.x * blockDim.x + threadIdx.x) * 2;
    if (e >= EE) return;
    int2 r = *(const int2*)&row[e];
    int2 c = *(const int2*)&col[e];
    int pc0 = atomicAdd(&g_curC[c.x], 1);
    int pr0 = atomicAdd(&g_curR[r.x], 1);
    int pc1 = atomicAdd(&g_curC[c.y], 1);
    int pr1 = atomicAdd(&g_curR[r.y], 1);
    g_sortedR[pc0] = r.x;
    g_sortedC[pr0] = c.x;
    g_sortedR[pc1] = r.y;
    g_sortedC[pr1] = c.y;
}

// ------- GEMM1: tf32 wmma, 2-stage cp.async, padded smem, 3 CTAs/SM ----------
// stage = A 128x36 (pad) + B 32x68 (pad) = 6784 floats = 26.5KB; 2 stages = 53KB
#define GM_BM 128
#define GM_BK 32
#define LDA 36
#define LDB 68
#define LDC 68
#define STG 6784
__global__ void __launch_bounds__(256, 3)
k_gemm1(const float* __restrict__ X, const float* __restrict__ W,
        const float* __restrict__ att) {
    extern __shared__ float smem[];
    int tid = threadIdx.x;
    int warp = tid >> 5;
    int wm = warp >> 1;
    int wn = warp & 1;
    int bm = blockIdx.x * GM_BM;

    wmma::fragment<wmma::accumulator, 16, 16, 8, float> acc[2][2];
#pragma unroll
    for (int i = 0; i < 2; i++)
#pragma unroll
        for (int j = 0; j < 2; j++) wmma::fill_fragment(acc[i][j], 0.f);

    // prefetch stage 0
    {
        float* sA = &smem[0];
        float* sB = &smem[GM_BM * LDA];
#pragma unroll
        for (int l = 0; l < 4; l++) {
            int p = tid + l * 256, m = p >> 3, k4 = (p & 7) << 2;
            cp16(&sA[m * LDA + k4], &X[(size_t)(bm + m) * FIN + k4], (bm + m) < NN);
        }
#pragma unroll
        for (int l = 0; l < 2; l++) {
            int p = tid + l * 256, k = p >> 4, n4 = (p & 15) << 2;
            cp16(&sB[k * LDB + n4], &W[(size_t)k * 64 + n4], true);
        }
        cp_commit();
    }

    int buf = 0;
    for (int k0 = 0; k0 < FIN; k0 += GM_BK) {
        int knext = k0 + GM_BK;
        if (knext < FIN) {             // prefetch next stage into buf^1
            float* sA = &smem[(buf ^ 1) * STG];
            float* sB = &smem[(buf ^ 1) * STG + GM_BM * LDA];
#pragma unroll
            for (int l = 0; l < 4; l++) {
                int p = tid + l * 256, m = p >> 3, k4 = (p & 7) << 2;
                cp16(&sA[m * LDA + k4], &X[(size_t)(bm + m) * FIN + knext + k4],
                     (bm + m) < NN);
            }
#pragma unroll
            for (int l = 0; l < 2; l++) {
                int p = tid + l * 256, k = p >> 4, n4 = (p & 15) << 2;
                cp16(&sB[k * LDB + n4], &W[(size_t)(knext + k) * 64 + n4], true);
            }
            cp_commit();
            asm volatile("cp.async.wait_group 1;");
        } else {
            asm volatile("cp.async.wait_group 0;");
        }
        __syncthreads();
        const float* sA = &smem[buf * STG];
        const float* sB = &smem[buf * STG + GM_BM * LDA];
#pragma unroll
        for (int kk = 0; kk < GM_BK; kk += 8) {
            wmma::fragment<wmma::matrix_a, 16, 16, 8, wmma::precision::tf32, wmma::row_major> a[2];
            wmma::fragment<wmma::matrix_b, 16, 16, 8, wmma::precision::tf32, wmma::row_major> b[2];
#pragma unroll
            for (int i = 0; i < 2; i++)
                wmma::load_matrix_sync(a[i], &sA[(wm * 32 + i * 16) * LDA + kk], LDA);
#pragma unroll
            for (int j = 0; j < 2; j++)
                wmma::load_matrix_sync(b[j], &sB[kk * LDB + wn * 32 + j * 16], LDB);
#pragma unroll
            for (int i = 0; i < 2; i++)
#pragma unroll
                for (int j = 0; j < 2; j++)
                    wmma::mma_sync(acc[i][j], a[i], b[j], acc[i][j]);
        }
        __syncthreads();
        buf ^= 1;
    }

    float* sC = smem;                  // 128 x 68 (padded)
#pragma unroll
    for (int i = 0; i < 2; i++)
#pragma unroll
        for (int j = 0; j < 2; j++)
            wmma::store_matrix_sync(&sC[(wm * 32 + i * 16) * LDC + wn * 32 + j * 16],
                                    acc[i][j], LDC, wmma::mem_row_major);
    __syncthreads();
    // fused scores: si -> g_sird[.x], sj -> g_sj
#pragma unroll
    for (int l = 0; l < 4; l++) {
        int p = tid + l * 256;
        int m = p >> 3, h = p & 7;
        if (bm + m < NN) {
            const float* xr = &sC[m * LDC + h * 8];
            float si = 0.f, sj = 0.f;
#pragma unroll
            for (int c = 0; c < 8; c++) {
                float v = xr[c];
                si += v * __ldg(&att[h * 16 + c]);
                sj += v * __ldg(&att[h * 16 + 8 + c]);
            }
            g_sird[((bm + m) * 8 + h) * 2] = si;
            g_sj[(bm + m) * 8 + h] = sj;
        }
    }
    // fp16 feature store: 4096 half2, 16 per thread
#pragma unroll
    for (int l = 0; l < 16; l++) {
        int p = tid + l * 256;
        int m = p >> 5, f2 = p & 31;
        if (bm + m < NN)
            g_xh_h[(size_t)(bm + m) * 32 + f2] =
                __floats2half2_rn(sC[m * LDC + f2 * 2], sC[m * LDC + f2 * 2 + 1]);
    }
}

// ---------------- denominator + Dinv (warp per node, by-row CSR) --------------
__global__ void k_den(const float* __restrict__ hw) {
    int w = (blockIdx.x * blockDim.x + threadIdx.x) >> 5;
    if (w >= NN) return;
    int lane = threadIdx.x & 31;
    int g = lane >> 3, h = lane & 7;
    int start = g_offR[w], end = g_offR[w + 1];
    float si_h = g_sird[(w * 8 + h) * 2];
    float den = 0.f, Dacc = 0.f;
    int i = start + g;
    for (; i + 4 < end; i += 8) {
        int c0 = g_sortedC[i];
        int c1 = g_sortedC[i + 4];
        float sj0 = __ldg(&g_sj[c0 * 8 + h]);
        float sj1 = __ldg(&g_sj[c1 * 8 + h]);
        den += __expf(lrelu(si_h + sj0)) + __expf(lrelu(si_h + sj1));
        if (h == 0) Dacc += __ldg(&hw[c0]) + __ldg(&hw[c1]);
    }
    if (i < end) {
        int c0 = g_sortedC[i];
        den += __expf(lrelu(si_h + __ldg(&g_sj[c0 * 8 + h])));
        if (h == 0) Dacc += __ldg(&hw[c0]);
    }
    den += __shfl_xor_sync(~0u, den, 8);
    den += __shfl_xor_sync(~0u, den, 16);
    Dacc += __shfl_xor_sync(~0u, Dacc, 8);
    Dacc += __shfl_xor_sync(~0u, Dacc, 16);
    if (g == 0) g_sird[(w * 8 + h) * 2 + 1] = 1.0f / (den + 1e-16f);
    if (lane == 0) g_Dinv[w] = Dacc > 0.f ? 1.0f / Dacc : 0.f;
}

// ---------------- prop1: nodes -> hyperedges (warp per hyperedge, fp16) -------
__global__ void k_prop1() {
    int w = (blockIdx.x * blockDim.x + threadIdx.x) >> 5;
    if (w >= NN) return;
    int lane = threadIdx.x & 31;
    int h = lane >> 2;
    int start = g_offC[w], end = g_offC[w + 1];
    float sj_h = g_sj[w * 8 + h];
    float binv = g_Binv[w];
    float ax = 0.f, ay = 0.f;
    int i = start;
    for (; i + 3 < end; i += 4) {
        int r0 = g_sortedR[i], r1 = g_sortedR[i + 1];
        int r2 = g_sortedR[i + 2], r3 = g_sortedR[i + 3];
        float2 sr0 = *(const float2*)&g_sird[(r0 * 8 + h) * 2];
        float2 sr1 = *(const float2*)&g_sird[(r1 * 8 + h) * 2];
        float2 sr2 = *(const float2*)&g_sird[(r2 * 8 + h) * 2];
        float2 sr3 = *(const float2*)&g_sird[(r3 * 8 + h) * 2];
        float2 f0 = __half22float2(g_xh_h[(size_t)r0 * 32 + lane]);
        float2 f1 = __half22float2(g_xh_h[(size_t)r1 * 32 + lane]);
        float2 f2 = __half22float2(g_xh_h[(size_t)r2 * 32 + lane]);
        float2 f3 = __half22float2(g_xh_h[(size_t)r3 * 32 + lane]);
        float w0 = __expf(lrelu(sr0.x + sj_h)) * sr0.y;
        float w1 = __expf(lrelu(sr1.x + sj_h)) * sr1.y;
        float w2 = __expf(lrelu(sr2.x + sj_h)) * sr2.y;
        float w3 = __expf(lrelu(sr3.x + sj_h)) * sr3.y;
        ax += w0 * f0.x + w1 * f1.x + w2 * f2.x + w3 * f3.x;
        ay += w0 * f0.y + w1 * f1.y + w2 * f2.y + w3 * f3.y;
    }
    for (; i < end; i++) {
        int r0 = g_sortedR[i];
        float2 sr0 = *(const float2*)&g_sird[(r0 * 8 + h) * 2];
        float2 f0 = __half22float2(g_xh_h[(size_t)r0 * 32 + lane]);
        float w0 = __expf(lrelu(sr0.x + sj_h)) * sr0.y;
        ax += w0 * f0.x; ay += w0 * f0.y;
    }
    g_oute_h[(size_t)w * 32 + lane] = __floats2half2_rn(ax * binv, ay * binv);
}

// ------- prop2 (fp16 gather) + bias + ELU + fused gemm2 (h1 never stored) -----
__global__ void k_prop2(const float* __restrict__ b1, const float* __restrict__ W2) {
    __shared__ float sW[448];
    for (int i = threadIdx.x; i < 448; i += 256) sW[i] = W2[i];
    __syncthreads();
    int w = (blockIdx.x * blockDim.x + threadIdx.x) >> 5;
    if (w >= NN) return;
    int lane = threadIdx.x & 31;
    int h = lane >> 2;
    int start = g_offR[w], end = g_offR[w + 1];
    float2 sr = *(const float2*)&g_sird[(w * 8 + h) * 2];
    float si_h = sr.x, rd_h = sr.y;
    float dinv = g_Dinv[w];
    float ax = 0.f, ay = 0.f;
    int i = start;
    for (; i + 3 < end; i += 4) {
        int c0 = g_sortedC[i], c1 = g_sortedC[i + 1];
        int c2 = g_sortedC[i + 2], c3 = g_sortedC[i + 3];
        float sj0 = __ldg(&g_sj[c0 * 8 + h]), sj1 = __ldg(&g_sj[c1 * 8 + h]);
        float sj2 = __ldg(&g_sj[c2 * 8 + h]), sj3 = __ldg(&g_sj[c3 * 8 + h]);
        float2 f0 = __half22float2(g_oute_h[(size_t)c0 * 32 + lane]);
        float2 f1 = __half22float2(g_oute_h[(size_t)c1 * 32 + lane]);
        float2 f2 = __half22float2(g_oute_h[(size_t)c2 * 32 + lane]);
        float2 f3 = __half22float2(g_oute_h[(size_t)c3 * 32 + lane]);
        float w0 = __expf(lrelu(si_h + sj0)) * rd_h;
        float w1 = __expf(lrelu(si_h + sj1)) * rd_h;
        float w2 = __expf(lrelu(si_h + sj2)) * rd_h;
        float w3 = __expf(lrelu(si_h + sj3)) * rd_h;
        ax += w0 * f0.x + w1 * f1.x + w2 * f2.x + w3 * f3.x;
        ay += w0 * f0.y + w1 * f1.y + w2 * f2.y + w3 * f3.y;
    }
    for (; i < end; i++) {
        int c0 = g_sortedC[i];
        float sj0 = __ldg(&g_sj[c0 * 8 + h]);
        float2 f0 = __half22float2(g_oute_h[(size_t)c0 * 32 + lane]);
        float w0 = __expf(lrelu(si_h + sj0)) * rd_h;
        ax += w0 * f0.x; ay += w0 * f0.y;
    }
    float vx = ax * dinv + __ldg(&b1[lane * 2]);
    float vy = ay * dinv + __ldg(&b1[lane * 2 + 1]);
    vx = vx > 0.f ? vx : expm1f(vx);
    vy = vy > 0.f ? vy : expm1f(vy);
    float a7[7];
#pragma unroll
    for (int j = 0; j < 7; j++)
        a7[j] = vx * sW[(lane * 2) * 7 + j] + vy * sW[(lane * 2 + 1) * 7 + j];
#pragma unroll
    for (int off = 16; off; off >>= 1)
#pragma unroll
        for (int j = 0; j < 7; j++)
            a7[j] += __shfl_xor_sync(~0u, a7[j], off);
    if (lane == 0) {
        float4* o = (float4*)&g_xh2[w * 8];
        o[0] = make_float4(a7[0], a7[1], a7[2], a7[3]);
        o[1] = make_float4(a7[4], a7[5], a7[6], 0.f);
    }
}

// ---------------- layer-2 propagation (warp per segment) ----------------------
__global__ void k2_prop1() {
    int w = (blockIdx.x * blockDim.x + threadIdx.x) >> 5;
    if (w >= NN) return;
    int lane = threadIdx.x & 31;
    int g = lane >> 3, j = lane & 7;
    int start = g_offC[w], end = g_offC[w + 1];
    float acc = 0.f;
    int i = start + g;
    for (; i + 4 < end; i += 8) {
        int r0 = g_sortedR[i], r1 = g_sortedR[i + 4];
        acc += __ldg(&g_xh2[r0 * 8 + j]) + __ldg(&g_xh2[r1 * 8 + j]);
    }
    if (i < end) acc += __ldg(&g_xh2[g_sortedR[i] * 8 + j]);
    acc += __shfl_xor_sync(~0u, acc, 8);
    acc += __shfl_xor_sync(~0u, acc, 16);
    if (g == 0) g_oute2[w * 8 + j] = acc * g_Binv[w];
}

// k2_prop2 + fused log_softmax
__global__ void k2_prop2(const float* __restrict__ b2, float* __restrict__ out) {
    int w = (blockIdx.x * blockDim.x + threadIdx.x) >> 5;
    if (w >= NN) return;
    int lane = threadIdx.x & 31;
    int g = lane >> 3, j = lane & 7;
    int start = g_offR[w], end = g_offR[w + 1];
    float acc = 0.f;
    int i = start + g;
    for (; i + 4 < end; i += 8) {
        int c0 = g_sortedC[i], c1 = g_sortedC[i + 4];
        acc += __ldg(&g_oute2[c0 * 8 + j]) + __ldg(&g_oute2[c1 * 8 + j]);
    }
    if (i < end) acc += __ldg(&g_oute2[g_sortedC[i] * 8 + j]);
    acc += __shfl_xor_sync(~0u, acc, 8);
    acc += __shfl_xor_sync(~0u, acc, 16);
    float v = (j < 7) ? acc * g_Dinv[w] + __ldg(&b2[j]) : -1e30f;
    float m = v;
#pragma unroll
    for (int off = 1; off < 8; off <<= 1)
        m = fmaxf(m, __shfl_xor_sync(~0u, m, off));
    float ex = (j < 7) ? __expf(v - m) : 0.f;
    float s = ex;
#pragma unroll
    for (int off = 1; off < 8; off <<= 1)
        s += __shfl_xor_sync(~0u, s, off);
    if (g == 0 && j < 7)
        out[(size_t)w * NCLS + j] = v - m - logf(s);
}

// ---------------- launch ------------------------------------------------------

extern "C" void kernel_launch(void* const* d_in, const int* in_sizes, int n_in,
                              void* d_out, int out_size) {
    const float* x   = (const float*)d_in[0];
    const int*   ei  = (const int*)  d_in[1];
    const float* hw  = (const float*)d_in[2];
    const float* W1  = (const float*)d_in[3];
    const float* att = (const float*)d_in[4];
    const float* b1  = (const float*)d_in[5];
    const float* W2  = (const float*)d_in[6];
    const float* b2  = (const float*)d_in[7];
    float* out = (float*)d_out;

    const int* row = ei;        // edge_index[0]
    const int* col = ei + EE;   // edge_index[1]

    const int EB2 = (EE / 2 + 255) / 256;     // 3125 (2 edges/thread)
    const int WB  = (NN * 32 + 255) / 256;    // 6250 (warp-per-segment kernels)
    const int GEMM_SMEM = 2 * STG * 4;        // 54272 bytes

    cudaFuncSetAttribute(k_gemm1, cudaFuncAttributeMaxDynamicSharedMemorySize,
                         GEMM_SMEM);

    k_count<<<EB2, 256>>>(row, col);
    k_bsum_scan<<<NB, 256>>>();
    k_scanfin<<<NB, 256>>>(hw);
    k_scatter<<<EB2, 256>>>(row, col);       // launch #4 -> ncu
    k_gemm1<<<(NN + GM_BM - 1) / GM_BM, 256, GEMM_SMEM>>>(x, W1, att);
    k_den<<<WB, 256>>>(hw);
    k_prop1<<<WB, 256>>>();
    k_prop2<<<WB, 256>>>(b1, W2);
    k2_prop1<<<WB, 256>>>();
    k2_prop2<<<WB, 256>>>(b2, out);
}